// round 12
// baseline (speedup 1.0000x reference)
#include <cuda_runtime.h>
#include <cuda_fp16.h>
#include <cstdint>

#define N_NODES 10000
#define DIM     256
#define E_MAX   320000
#define BKT     96            // bucket capacity per node (Poisson(32): mean+11σ)

#define MIN_NORM 1e-15f
#define MAXNORM  0.996f      // (1 - 4e-3)/sqrt(c), c = 1

// ---------------- device scratch (no allocations allowed) ----------------
typedef unsigned long long u64;

__device__ float   g_h  [N_NODES * DIM];    // current hyperbolic features (fp32)
__device__ __half  g_xt [N_NODES * DIM];    // tangent features (fp16)
__device__ float   g_x2 [N_NODES];          // sumsq of each g_h row
__device__ int     g_cnt[N_NODES];          // per-node degree counter
__device__ u64     g_bkt[N_NODES * BKT];    // packed (src, weight) pairs
__device__ float   g_bias[2][DIM];
__device__ float   g_by2[2];                // sumsq of hyp_bias per layer

// ---------------- packed f32x2 helpers (sm_100+ PTX) ------
#define FMA2(d, a, b, c) \
    asm("fma.rn.f32x2 %0, %1, %2, %3;" : "=l"(d) : "l"(a), "l"(b), "l"(c))

__device__ __forceinline__ u64 pack_dup(float a) {
    u64 r;
    asm("mov.b64 %0, {%1, %1};" : "=l"(r) : "r"(__float_as_uint(a)));
    return r;
}
__device__ __forceinline__ u64 pack2(float lo, float hi) {
    u64 r;
    asm("mov.b64 %0, {%1, %2};" : "=l"(r) : "r"(__float_as_uint(lo)), "r"(__float_as_uint(hi)));
    return r;
}
__device__ __forceinline__ float lo_f(u64 v) { return __uint_as_float((uint32_t)v); }
__device__ __forceinline__ float hi_f(u64 v) { return __uint_as_float((uint32_t)(v >> 32)); }

// ---------------- math helpers ----------------
__device__ __forceinline__ float artanh_clip(float x) {
    x = fminf(fmaxf(x, -1.0f + 1e-7f), 1.0f - 1e-7f);
    return atanhf(x);
}

__device__ __forceinline__ float wsum(float v) {
    #pragma unroll
    for (int o = 16; o > 0; o >>= 1) v += __shfl_xor_sync(0xffffffffu, v, o);
    return v;
}

// ---------------- bucket build ----------------
__global__ void zero_k(int n) {
    int i = blockIdx.x * blockDim.x + threadIdx.x;
    if (i < n) g_cnt[i] = 0;
}

__global__ void fillb_k(const int* __restrict__ src, const int* __restrict__ dst,
                        const float* __restrict__ w, int E) {
    int e = blockIdx.x * blockDim.x + threadIdx.x;
    if (e < E) {
        int d = dst[e];
        int slot = atomicAdd(&g_cnt[d], 1);
        if (slot < BKT) {
            u64 pair = (u64)(uint32_t)src[e] | ((u64)__float_as_uint(w[e]) << 32);
            g_bkt[(size_t)d * BKT + slot] = pair;
        }
    }
}

// ---------------- init: warp-per-row, barrier-free ----------
__global__ void init_k(const float* __restrict__ x,
                       const float* __restrict__ b1,
                       const float* __restrict__ b2, int n) {
    int w = threadIdx.x >> 5, lane = threadIdx.x & 31;
    int i = blockIdx.x * 8 + w;
    if (i >= n + 2) return;
    bool is_bias = (i >= n);
    const float* srcv = is_bias ? ((i == n) ? b1 : b2) : x + (size_t)i * DIM;

    float4 v0 = *(const float4*)&srcv[lane * 8];
    float4 v1 = *(const float4*)&srcv[lane * 8 + 4];

    float p = v0.x * v0.x + v0.y * v0.y + v0.z * v0.z + v0.w * v0.w
            + v1.x * v1.x + v1.y * v1.y + v1.z * v1.z + v1.w * v1.w;
    float s1 = wsum(p);
    float nn = fmaxf(sqrtf(s1), MIN_NORM);
    float f  = tanhf(nn) / nn;                 // expmap0
    float s  = s1 * f * f;
    float n2 = fmaxf(sqrtf(s), MIN_NORM);      // proj (analytic)
    if (n2 > MAXNORM) { f *= MAXNORM / n2; s = MAXNORM * MAXNORM; }
    v0.x *= f; v0.y *= f; v0.z *= f; v0.w *= f;
    v1.x *= f; v1.y *= f; v1.z *= f; v1.w *= f;

    if (is_bias) {
        int L = i - n;
        *(float4*)&g_bias[L][lane * 8]     = v0;
        *(float4*)&g_bias[L][lane * 8 + 4] = v1;
        if (lane == 0) g_by2[L] = s;
    } else {
        *(float4*)&g_h[(size_t)i * DIM + lane * 8]     = v0;
        *(float4*)&g_h[(size_t)i * DIM + lane * 8 + 4] = v1;
        if (lane == 0) g_x2[i] = s;
    }
}

// ---------------- fused GEMM (f32x2) + HypLinear tail -> g_xt ----------
// mx = h @ W^T. BM=32 rows/CTA; 8 warps x 4 rows; lane owns 8 consecutive
// columns 8*lane..8*lane+7 (4 f32x2 pairs). Mainloop per k: 1 LDS.128
// broadcast (4 A row values) + 2 LDS.128 (8 B values) + 16 FMA2.
#define GBM 32
#define GBK 16
#define AP  36                 // 36*4 = 144 B row stride (16B aligned)
#define BP  260                // 260*4 = 1040 B row stride (16B aligned)

__global__ __launch_bounds__(256, 3) void gemm_fused_k(const float* __restrict__ W,
                                                       int layer, int M) {
    __shared__ float As[GBK][AP];
    __shared__ float Bs[GBK][BP];
    int tid = threadIdx.x;
    int bm  = blockIdx.x * GBM;
    int lane = tid & 31;
    int ty   = tid >> 5;       // warp 0..7: rows bm + ty*4 .. +3

    u64 acc[4][4];
    #pragma unroll
    for (int i = 0; i < 4; i++)
        #pragma unroll
        for (int j = 0; j < 4; j++) acc[i][j] = 0ull;

    int a_r = tid >> 3;            // 0..31
    int a_k = (tid & 7) << 1;      // 0,2,..,14
    int b_j = tid >> 2;            // 0..63 (+64q)
    int b_k = (tid & 3) << 2;      // 0,4,8,12

    for (int k0 = 0; k0 < DIM; k0 += GBK) {
        {
            int r = bm + a_r;
            float2 v = make_float2(0.f, 0.f);
            if (r < M) v = *(const float2*)&g_h[(size_t)r * DIM + k0 + a_k];
            As[a_k + 0][a_r] = v.x;
            As[a_k + 1][a_r] = v.y;
        }
        #pragma unroll
        for (int q = 0; q < 4; q++) {
            int j = b_j + 64 * q;
            float4 v = *(const float4*)&W[(size_t)j * DIM + k0 + b_k];
            Bs[b_k + 0][j] = v.x;
            Bs[b_k + 1][j] = v.y;
            Bs[b_k + 2][j] = v.z;
            Bs[b_k + 3][j] = v.w;
        }
        __syncthreads();
        #pragma unroll
        for (int k = 0; k < GBK; k++) {
            float4 a4 = *(const float4*)&As[k][ty * 4];           // broadcast
            float4 bA = *(const float4*)&Bs[k][8 * lane];
            float4 bB = *(const float4*)&Bs[k][8 * lane + 4];
            u64 bp0 = pack2(bA.x, bA.y);
            u64 bp1 = pack2(bA.z, bA.w);
            u64 bp2 = pack2(bB.x, bB.y);
            u64 bp3 = pack2(bB.z, bB.w);
            u64 a0 = pack_dup(a4.x);
            u64 a1 = pack_dup(a4.y);
            u64 a2 = pack_dup(a4.z);
            u64 a3 = pack_dup(a4.w);
            FMA2(acc[0][0], a0, bp0, acc[0][0]);
            FMA2(acc[0][1], a0, bp1, acc[0][1]);
            FMA2(acc[0][2], a0, bp2, acc[0][2]);
            FMA2(acc[0][3], a0, bp3, acc[0][3]);
            FMA2(acc[1][0], a1, bp0, acc[1][0]);
            FMA2(acc[1][1], a1, bp1, acc[1][1]);
            FMA2(acc[1][2], a1, bp2, acc[1][2]);
            FMA2(acc[1][3], a1, bp3, acc[1][3]);
            FMA2(acc[2][0], a2, bp0, acc[2][0]);
            FMA2(acc[2][1], a2, bp1, acc[2][1]);
            FMA2(acc[2][2], a2, bp2, acc[2][2]);
            FMA2(acc[2][3], a2, bp3, acc[2][3]);
            FMA2(acc[3][0], a3, bp0, acc[3][0]);
            FMA2(acc[3][1], a3, bp1, acc[3][1]);
            FMA2(acc[3][2], a3, bp2, acc[3][2]);
            FMA2(acc[3][3], a3, bp3, acc[3][3]);
        }
        __syncthreads();
    }

    // ---- epilogue: 2 warp reductions, rest analytic ----
    // lane owns cols 8*lane + {0..7}; pair j covers cols 8*lane+2j, +1.
    float4 yv0 = *(const float4*)&g_bias[layer][lane * 8];
    float4 yv1 = *(const float4*)&g_bias[layer][lane * 8 + 4];
    float y[8] = {yv0.x, yv0.y, yv0.z, yv0.w, yv1.x, yv1.y, yv1.z, yv1.w};
    float y2 = g_by2[layer];

    #pragma unroll
    for (int i = 0; i < 4; i++) {
        int row = bm + ty * 4 + i;
        if (row >= M) continue;

        float mxv[8];
        #pragma unroll
        for (int j = 0; j < 4; j++) {
            mxv[2 * j]     = lo_f(acc[i][j]);
            mxv[2 * j + 1] = hi_f(acc[i][j]);
        }

        float msq = 0.0f;
        #pragma unroll
        for (int j = 0; j < 8; j++) msq = fmaf(mxv[j], mxv[j], msq);
        float m2s = wsum(msq);                         // reduction #1

        float res[8];
        float x2;
        if (m2s == 0.0f) {
            #pragma unroll
            for (int j = 0; j < 8; j++) res[j] = 0.0f;
            x2 = 0.0f;
        } else {
            float x_norm = fmaxf(sqrtf(g_x2[row]), MIN_NORM);
            float mxn = fmaxf(sqrtf(m2s), MIN_NORM);
            float sc = tanhf(mxn / x_norm * artanh_clip(x_norm)) / mxn;
            #pragma unroll
            for (int j = 0; j < 8; j++) res[j] = mxv[j] * sc;
            x2 = m2s * sc * sc;
            float n = fmaxf(sqrtf(x2), MIN_NORM);      // proj (analytic)
            if (n > MAXNORM) {
                float g = MAXNORM / n;
                #pragma unroll
                for (int j = 0; j < 8; j++) res[j] *= g;
                x2 = MAXNORM * MAXNORM;
            }
        }

        float pxy = 0.0f;
        #pragma unroll
        for (int j = 0; j < 8; j++) pxy = fmaf(res[j], y[j], pxy);
        float xy = wsum(pxy);                          // reduction #2

        float ca  = 1.0f + 2.0f * xy + y2;
        float cb  = 1.0f - x2;
        float den = fmaxf(1.0f + 2.0f * xy + x2 * y2, MIN_NORM);
        float inv = 1.0f / den;
        float hv[8];
        #pragma unroll
        for (int j = 0; j < 8; j++) hv[j] = (ca * res[j] + cb * y[j]) * inv;
        float h2 = inv * inv * (ca * ca * x2 + 2.0f * ca * cb * xy + cb * cb * y2);

        float n = fmaxf(sqrtf(h2), MIN_NORM);          // proj (analytic)
        if (n > MAXNORM) {
            float g = MAXNORM / n;
            #pragma unroll
            for (int j = 0; j < 8; j++) hv[j] *= g;
            h2 = MAXNORM * MAXNORM;
        }
        float pn = fmaxf(sqrtf(h2), MIN_NORM);         // logmap0 (analytic)
        float ls = artanh_clip(pn) / pn;

        __half2 o0 = __floats2half2_rn(hv[0] * ls, hv[1] * ls);
        __half2 o1 = __floats2half2_rn(hv[2] * ls, hv[3] * ls);
        __half2 o2 = __floats2half2_rn(hv[4] * ls, hv[5] * ls);
        __half2 o3 = __floats2half2_rn(hv[6] * ls, hv[7] * ls);
        uint4 ov = make_uint4(*(uint32_t*)&o0, *(uint32_t*)&o1,
                              *(uint32_t*)&o2, *(uint32_t*)&o3);
        *(uint4*)&g_xt[(size_t)row * DIM + lane * 8] = ov;
    }
}

// ---------------- aggregation: warp-per-row, 4-edge MLP batches ----------
__global__ __launch_bounds__(256) void agg_k(float* __restrict__ out_opt, int n) {
    int w = threadIdx.x >> 5, lane = threadIdx.x & 31;
    int i = blockIdx.x * 8 + w;
    if (i >= n) return;
    int deg = min(g_cnt[i], BKT);
    const u64* bkt = &g_bkt[(size_t)i * BKT];

    float acc[8];
    #pragma unroll
    for (int j = 0; j < 8; j++) acc[j] = 0.0f;

    for (int base = 0; base < deg; base += 32) {
        int cnt = min(32, deg - base);
        int   myi = 0;
        float myw = 0.0f;
        if (lane < cnt) {
            u64 pair = bkt[base + lane];
            myi = (int)(uint32_t)pair;
            myw = __uint_as_float((uint32_t)(pair >> 32));
        }
        int e = 0;
        for (; e + 4 <= cnt; e += 4) {
            int   s0 = __shfl_sync(0xffffffffu, myi, e + 0);
            int   s1 = __shfl_sync(0xffffffffu, myi, e + 1);
            int   s2 = __shfl_sync(0xffffffffu, myi, e + 2);
            int   s3 = __shfl_sync(0xffffffffu, myi, e + 3);
            float w0 = __shfl_sync(0xffffffffu, myw, e + 0);
            float w1 = __shfl_sync(0xffffffffu, myw, e + 1);
            float w2 = __shfl_sync(0xffffffffu, myw, e + 2);
            float w3 = __shfl_sync(0xffffffffu, myw, e + 3);
            uint4 r0 = *(const uint4*)&g_xt[(size_t)s0 * DIM + lane * 8];
            uint4 r1 = *(const uint4*)&g_xt[(size_t)s1 * DIM + lane * 8];
            uint4 r2 = *(const uint4*)&g_xt[(size_t)s2 * DIM + lane * 8];
            uint4 r3 = *(const uint4*)&g_xt[(size_t)s3 * DIM + lane * 8];
            {
                float2 p0 = __half22float2(*(__half2*)&r0.x);
                float2 p1 = __half22float2(*(__half2*)&r0.y);
                float2 p2 = __half22float2(*(__half2*)&r0.z);
                float2 p3 = __half22float2(*(__half2*)&r0.w);
                acc[0] = fmaf(w0, p0.x, acc[0]); acc[1] = fmaf(w0, p0.y, acc[1]);
                acc[2] = fmaf(w0, p1.x, acc[2]); acc[3] = fmaf(w0, p1.y, acc[3]);
                acc[4] = fmaf(w0, p2.x, acc[4]); acc[5] = fmaf(w0, p2.y, acc[5]);
                acc[6] = fmaf(w0, p3.x, acc[6]); acc[7] = fmaf(w0, p3.y, acc[7]);
            }
            {
                float2 p0 = __half22float2(*(__half2*)&r1.x);
                float2 p1 = __half22float2(*(__half2*)&r1.y);
                float2 p2 = __half22float2(*(__half2*)&r1.z);
                float2 p3 = __half22float2(*(__half2*)&r1.w);
                acc[0] = fmaf(w1, p0.x, acc[0]); acc[1] = fmaf(w1, p0.y, acc[1]);
                acc[2] = fmaf(w1, p1.x, acc[2]); acc[3] = fmaf(w1, p1.y, acc[3]);
                acc[4] = fmaf(w1, p2.x, acc[4]); acc[5] = fmaf(w1, p2.y, acc[5]);
                acc[6] = fmaf(w1, p3.x, acc[6]); acc[7] = fmaf(w1, p3.y, acc[7]);
            }
            {
                float2 p0 = __half22float2(*(__half2*)&r2.x);
                float2 p1 = __half22float2(*(__half2*)&r2.y);
                float2 p2 = __half22float2(*(__half2*)&r2.z);
                float2 p3 = __half22float2(*(__half2*)&r2.w);
                acc[0] = fmaf(w2, p0.x, acc[0]); acc[1] = fmaf(w2, p0.y, acc[1]);
                acc[2] = fmaf(w2, p1.x, acc[2]); acc[3] = fmaf(w2, p1.y, acc[3]);
                acc[4] = fmaf(w2, p2.x, acc[4]); acc[5] = fmaf(w2, p2.y, acc[5]);
                acc[6] = fmaf(w2, p3.x, acc[6]); acc[7] = fmaf(w2, p3.y, acc[7]);
            }
            {
                float2 p0 = __half22float2(*(__half2*)&r3.x);
                float2 p1 = __half22float2(*(__half2*)&r3.y);
                float2 p2 = __half22float2(*(__half2*)&r3.z);
                float2 p3 = __half22float2(*(__half2*)&r3.w);
                acc[0] = fmaf(w3, p0.x, acc[0]); acc[1] = fmaf(w3, p0.y, acc[1]);
                acc[2] = fmaf(w3, p1.x, acc[2]); acc[3] = fmaf(w3, p1.y, acc[3]);
                acc[4] = fmaf(w3, p2.x, acc[4]); acc[5] = fmaf(w3, p2.y, acc[5]);
                acc[6] = fmaf(w3, p3.x, acc[6]); acc[7] = fmaf(w3, p3.y, acc[7]);
            }
        }
        for (; e < cnt; e++) {
            int   src = __shfl_sync(0xffffffffu, myi, e);
            float wt  = __shfl_sync(0xffffffffu, myw, e);
            uint4 raw = *(const uint4*)&g_xt[(size_t)src * DIM + lane * 8];
            float2 p0 = __half22float2(*(__half2*)&raw.x);
            float2 p1 = __half22float2(*(__half2*)&raw.y);
            float2 p2 = __half22float2(*(__half2*)&raw.z);
            float2 p3 = __half22float2(*(__half2*)&raw.w);
            acc[0] = fmaf(wt, p0.x, acc[0]); acc[1] = fmaf(wt, p0.y, acc[1]);
            acc[2] = fmaf(wt, p1.x, acc[2]); acc[3] = fmaf(wt, p1.y, acc[3]);
            acc[4] = fmaf(wt, p2.x, acc[4]); acc[5] = fmaf(wt, p2.y, acc[5]);
            acc[6] = fmaf(wt, p3.x, acc[6]); acc[7] = fmaf(wt, p3.y, acc[7]);
        }
    }

    // tail: 2 warp reductions, rest analytic
    float p = 0.0f;
    #pragma unroll
    for (int j = 0; j < 8; j++) p = fmaf(acc[j], acc[j], p);
    float s1 = wsum(p);                                // reduction #1
    float n1 = fmaxf(sqrtf(s1), MIN_NORM);
    float f1 = tanhf(n1) / n1;                         // expmap0
    float s  = s1 * f1 * f1;
    float n2 = fmaxf(sqrtf(s), MIN_NORM);              // proj (analytic)
    if (n2 > MAXNORM) { f1 *= MAXNORM / n2; s = MAXNORM * MAXNORM; }
    float n3 = fmaxf(sqrtf(s), MIN_NORM);              // logmap0 (analytic)
    float ls = artanh_clip(n3) / n3;
    float g1 = f1 * ls;
    #pragma unroll
    for (int j = 0; j < 8; j++) acc[j] = fmaxf(acc[j] * g1, 0.0f);  // relu

    p = 0.0f;
    #pragma unroll
    for (int j = 0; j < 8; j++) p = fmaf(acc[j], acc[j], p);
    float s5 = wsum(p);                                // reduction #2
    float n5 = fmaxf(sqrtf(s5), MIN_NORM);
    float f2 = tanhf(n5) / n5;                         // expmap0
    s = s5 * f2 * f2;
    float n6 = fmaxf(sqrtf(s), MIN_NORM);              // proj (analytic)
    if (n6 > MAXNORM) { f2 *= MAXNORM / n6; s = MAXNORM * MAXNORM; }
    #pragma unroll
    for (int j = 0; j < 8; j++) acc[j] *= f2;

    float4 o0 = make_float4(acc[0], acc[1], acc[2], acc[3]);
    float4 o1 = make_float4(acc[4], acc[5], acc[6], acc[7]);
    if (out_opt) {
        *(float4*)&out_opt[(size_t)i * DIM + lane * 8]     = o0;
        *(float4*)&out_opt[(size_t)i * DIM + lane * 8 + 4] = o1;
    } else {
        *(float4*)&g_h[(size_t)i * DIM + lane * 8]     = o0;
        *(float4*)&g_h[(size_t)i * DIM + lane * 8 + 4] = o1;
        if (lane == 0) g_x2[i] = s;
    }
}

// ---------------- launch ----------------
extern "C" void kernel_launch(void* const* d_in, const int* in_sizes, int n_in,
                              void* d_out, int out_size) {
    const float* x    = (const float*)d_in[0];
    const float* W1   = (const float*)d_in[1];
    const float* b1   = (const float*)d_in[2];
    const float* W2   = (const float*)d_in[3];
    const float* b2   = (const float*)d_in[4];
    const float* ew   = (const float*)d_in[5];
    const int*   esrc = (const int*)d_in[6];
    const int*   edst = (const int*)d_in[7];
    float*       out  = (float*)d_out;

    int n = in_sizes[0] / DIM;   // 10000
    int E = in_sizes[5];         // 320000

    // Fork the bucket build onto a side stream; overlap with init + gemm1.
    // Streams/events created only on non-replay calls; never destroyed here.
    cudaStream_t s2;
    cudaEvent_t e1, e2;
    cudaStreamCreateWithFlags(&s2, cudaStreamNonBlocking);
    cudaEventCreateWithFlags(&e1, cudaEventDisableTiming);
    cudaEventCreateWithFlags(&e2, cudaEventDisableTiming);

    // kernel-launch order: init(0), zero(1), fillb(2), gemm1(3), agg1(4),
    // gemm2(5) <- ncu -s 5 profiles the GEMM, agg2(6)
    init_k<<<(n + 2 + 7) / 8, 256>>>(x, b1, b2, n);

    cudaEventRecord(e1, 0);
    cudaStreamWaitEvent(s2, e1, 0);
    zero_k<<<(n + 255) / 256, 256, 0, s2>>>(n);
    fillb_k<<<(E + 255) / 256, 256, 0, s2>>>(esrc, edst, ew, E);
    cudaEventRecord(e2, s2);

    int gblocks = (n + GBM - 1) / GBM;   // 313

    gemm_fused_k<<<gblocks, 256>>>(W1, 0, n);

    cudaStreamWaitEvent(0, e2, 0);
    agg_k<<<(n + 7) / 8, 256>>>(nullptr, n);

    gemm_fused_k<<<gblocks, 256>>>(W2, 1, n);
    agg_k<<<(n + 7) / 8, 256>>>(out, n);
}

// round 13
// speedup vs baseline: 1.8004x; 1.8004x over previous
#include <cuda_runtime.h>
#include <cuda_fp16.h>
#include <cstdint>

#define N_NODES 10000
#define DIM     256
#define E_MAX   320000
#define BKT     96            // bucket capacity per node (Poisson(32): mean+11σ)

#define MIN_NORM 1e-15f
#define MAXNORM  0.996f      // (1 - 4e-3)/sqrt(c), c = 1

// ---------------- device scratch (no allocations allowed) ----------------
typedef unsigned long long u64;

__device__ float   g_h  [N_NODES * DIM];    // current hyperbolic features (fp32)
__device__ __half  g_xt [N_NODES * DIM];    // tangent features (fp16)
__device__ float   g_x2 [N_NODES];          // sumsq of each g_h row
__device__ int     g_cnt[N_NODES];          // per-node degree counter
__device__ u64     g_bkt[N_NODES * BKT];    // packed (src, weight) pairs
__device__ float   g_bias[2][DIM];
__device__ float   g_by2[2];                // sumsq of hyp_bias per layer

// ---------------- packed f32x2 helpers (sm_100+ PTX) ------
#define FMA2(d, a, b, c) \
    asm("fma.rn.f32x2 %0, %1, %2, %3;" : "=l"(d) : "l"(a), "l"(b), "l"(c))

__device__ __forceinline__ u64 pack_dup(float a) {
    u64 r;
    asm("mov.b64 %0, {%1, %1};" : "=l"(r) : "r"(__float_as_uint(a)));
    return r;
}
__device__ __forceinline__ u64 pack2(float lo, float hi) {
    u64 r;
    asm("mov.b64 %0, {%1, %2};" : "=l"(r) : "r"(__float_as_uint(lo)), "r"(__float_as_uint(hi)));
    return r;
}
__device__ __forceinline__ float lo_f(u64 v) { return __uint_as_float((uint32_t)v); }
__device__ __forceinline__ float hi_f(u64 v) { return __uint_as_float((uint32_t)(v >> 32)); }

// ---------------- math helpers ----------------
__device__ __forceinline__ float artanh_clip(float x) {
    x = fminf(fmaxf(x, -1.0f + 1e-7f), 1.0f - 1e-7f);
    return atanhf(x);
}

__device__ __forceinline__ float wsum(float v) {
    #pragma unroll
    for (int o = 16; o > 0; o >>= 1) v += __shfl_xor_sync(0xffffffffu, v, o);
    return v;
}

// ---------------- bucket build ----------------
__global__ void zero_k(int n) {
    int i = blockIdx.x * blockDim.x + threadIdx.x;
    if (i < n) g_cnt[i] = 0;
}

__global__ void fillb_k(const int* __restrict__ src, const int* __restrict__ dst,
                        const float* __restrict__ w, int E) {
    int e = blockIdx.x * blockDim.x + threadIdx.x;
    if (e < E) {
        int d = dst[e];
        int slot = atomicAdd(&g_cnt[d], 1);
        if (slot < BKT) {
            u64 pair = (u64)(uint32_t)src[e] | ((u64)__float_as_uint(w[e]) << 32);
            g_bkt[(size_t)d * BKT + slot] = pair;
        }
    }
}

// ---------------- init: warp-per-row, barrier-free ----------
__global__ void init_k(const float* __restrict__ x,
                       const float* __restrict__ b1,
                       const float* __restrict__ b2, int n) {
    int w = threadIdx.x >> 5, lane = threadIdx.x & 31;
    int i = blockIdx.x * 8 + w;
    if (i >= n + 2) return;
    bool is_bias = (i >= n);
    const float* srcv = is_bias ? ((i == n) ? b1 : b2) : x + (size_t)i * DIM;

    float4 v0 = *(const float4*)&srcv[lane * 8];
    float4 v1 = *(const float4*)&srcv[lane * 8 + 4];

    float p = v0.x * v0.x + v0.y * v0.y + v0.z * v0.z + v0.w * v0.w
            + v1.x * v1.x + v1.y * v1.y + v1.z * v1.z + v1.w * v1.w;
    float s1 = wsum(p);
    float nn = fmaxf(sqrtf(s1), MIN_NORM);
    float f  = tanhf(nn) / nn;                 // expmap0
    float s  = s1 * f * f;
    float n2 = fmaxf(sqrtf(s), MIN_NORM);      // proj (analytic)
    if (n2 > MAXNORM) { f *= MAXNORM / n2; s = MAXNORM * MAXNORM; }
    v0.x *= f; v0.y *= f; v0.z *= f; v0.w *= f;
    v1.x *= f; v1.y *= f; v1.z *= f; v1.w *= f;

    if (is_bias) {
        int L = i - n;
        *(float4*)&g_bias[L][lane * 8]     = v0;
        *(float4*)&g_bias[L][lane * 8 + 4] = v1;
        if (lane == 0) g_by2[L] = s;
    } else {
        *(float4*)&g_h[(size_t)i * DIM + lane * 8]     = v0;
        *(float4*)&g_h[(size_t)i * DIM + lane * 8 + 4] = v1;
        if (lane == 0) g_x2[i] = s;
    }
}

// ---------------- fused GEMM (f32x2) + HypLinear tail -> g_xt ----------
// mx = h @ W^T. BM=32 rows/CTA; 8 warps x 4 rows; lane owns cols
// {4*lane + 128*j + c}, j in {0,1}, c in {0..3}: B read = 2x LDS.128 with
// 16-byte lane stride (conflict-free), A read = 1x LDS.128 broadcast.
#define GBM 32
#define GBK 16
#define AP  36                 // 36*4 = 144 B row stride (16B aligned)
#define BP  260                // 260*4 = 1040 B row stride (16B aligned)

__global__ __launch_bounds__(256, 3) void gemm_fused_k(const float* __restrict__ W,
                                                       int layer, int M) {
    __shared__ float As[GBK][AP];
    __shared__ float Bs[GBK][BP];
    int tid = threadIdx.x;
    int bm  = blockIdx.x * GBM;
    int lane = tid & 31;
    int ty   = tid >> 5;       // warp 0..7: rows bm + ty*4 .. +3

    u64 acc[4][4];
    #pragma unroll
    for (int i = 0; i < 4; i++)
        #pragma unroll
        for (int j = 0; j < 4; j++) acc[i][j] = 0ull;

    int a_r = tid >> 3;            // 0..31
    int a_k = (tid & 7) << 1;      // 0,2,..,14
    int b_j = tid >> 2;            // 0..63 (+64q)
    int b_k = (tid & 3) << 2;      // 0,4,8,12

    for (int k0 = 0; k0 < DIM; k0 += GBK) {
        {
            int r = bm + a_r;
            float2 v = make_float2(0.f, 0.f);
            if (r < M) v = *(const float2*)&g_h[(size_t)r * DIM + k0 + a_k];
            As[a_k + 0][a_r] = v.x;
            As[a_k + 1][a_r] = v.y;
        }
        #pragma unroll
        for (int q = 0; q < 4; q++) {
            int j = b_j + 64 * q;
            float4 v = *(const float4*)&W[(size_t)j * DIM + k0 + b_k];
            Bs[b_k + 0][j] = v.x;
            Bs[b_k + 1][j] = v.y;
            Bs[b_k + 2][j] = v.z;
            Bs[b_k + 3][j] = v.w;
        }
        __syncthreads();
        #pragma unroll
        for (int k = 0; k < GBK; k++) {
            float4 a4 = *(const float4*)&As[k][ty * 4];            // broadcast
            float4 bA = *(const float4*)&Bs[k][4 * lane];          // 16B stride
            float4 bB = *(const float4*)&Bs[k][4 * lane + 128];    // 16B stride
            u64 bp0 = pack2(bA.x, bA.y);
            u64 bp1 = pack2(bA.z, bA.w);
            u64 bp2 = pack2(bB.x, bB.y);
            u64 bp3 = pack2(bB.z, bB.w);
            u64 a0 = pack_dup(a4.x);
            u64 a1 = pack_dup(a4.y);
            u64 a2 = pack_dup(a4.z);
            u64 a3 = pack_dup(a4.w);
            FMA2(acc[0][0], a0, bp0, acc[0][0]);
            FMA2(acc[0][1], a0, bp1, acc[0][1]);
            FMA2(acc[0][2], a0, bp2, acc[0][2]);
            FMA2(acc[0][3], a0, bp3, acc[0][3]);
            FMA2(acc[1][0], a1, bp0, acc[1][0]);
            FMA2(acc[1][1], a1, bp1, acc[1][1]);
            FMA2(acc[1][2], a1, bp2, acc[1][2]);
            FMA2(acc[1][3], a1, bp3, acc[1][3]);
            FMA2(acc[2][0], a2, bp0, acc[2][0]);
            FMA2(acc[2][1], a2, bp1, acc[2][1]);
            FMA2(acc[2][2], a2, bp2, acc[2][2]);
            FMA2(acc[2][3], a2, bp3, acc[2][3]);
            FMA2(acc[3][0], a3, bp0, acc[3][0]);
            FMA2(acc[3][1], a3, bp1, acc[3][1]);
            FMA2(acc[3][2], a3, bp2, acc[3][2]);
            FMA2(acc[3][3], a3, bp3, acc[3][3]);
        }
        __syncthreads();
    }

    // ---- epilogue: 2 warp reductions, rest analytic ----
    // pair j: j=0 -> cols 4L+0,1; j=1 -> 4L+2,3; j=2 -> 4L+128,129; j=3 -> 4L+130,131
    int c0 = 4 * lane;
    float4 yv0 = *(const float4*)&g_bias[layer][c0];
    float4 yv1 = *(const float4*)&g_bias[layer][c0 + 128];
    float y[8] = {yv0.x, yv0.y, yv0.z, yv0.w, yv1.x, yv1.y, yv1.z, yv1.w};
    float y2 = g_by2[layer];

    #pragma unroll
    for (int i = 0; i < 4; i++) {
        int row = bm + ty * 4 + i;
        if (row >= M) continue;

        float mxv[8];
        #pragma unroll
        for (int j = 0; j < 4; j++) {
            mxv[2 * j]     = lo_f(acc[i][j]);
            mxv[2 * j + 1] = hi_f(acc[i][j]);
        }

        float msq = 0.0f;
        #pragma unroll
        for (int j = 0; j < 8; j++) msq = fmaf(mxv[j], mxv[j], msq);
        float m2s = wsum(msq);                         // reduction #1

        float res[8];
        float x2;
        if (m2s == 0.0f) {
            #pragma unroll
            for (int j = 0; j < 8; j++) res[j] = 0.0f;
            x2 = 0.0f;
        } else {
            float x_norm = fmaxf(sqrtf(g_x2[row]), MIN_NORM);
            float mxn = fmaxf(sqrtf(m2s), MIN_NORM);
            float sc = tanhf(mxn / x_norm * artanh_clip(x_norm)) / mxn;
            #pragma unroll
            for (int j = 0; j < 8; j++) res[j] = mxv[j] * sc;
            x2 = m2s * sc * sc;
            float n = fmaxf(sqrtf(x2), MIN_NORM);      // proj (analytic)
            if (n > MAXNORM) {
                float g = MAXNORM / n;
                #pragma unroll
                for (int j = 0; j < 8; j++) res[j] *= g;
                x2 = MAXNORM * MAXNORM;
            }
        }

        float pxy = 0.0f;
        #pragma unroll
        for (int j = 0; j < 8; j++) pxy = fmaf(res[j], y[j], pxy);
        float xy = wsum(pxy);                          // reduction #2

        float ca  = 1.0f + 2.0f * xy + y2;
        float cb  = 1.0f - x2;
        float den = fmaxf(1.0f + 2.0f * xy + x2 * y2, MIN_NORM);
        float inv = 1.0f / den;
        float hv[8];
        #pragma unroll
        for (int j = 0; j < 8; j++) hv[j] = (ca * res[j] + cb * y[j]) * inv;
        float h2 = inv * inv * (ca * ca * x2 + 2.0f * ca * cb * xy + cb * cb * y2);

        float n = fmaxf(sqrtf(h2), MIN_NORM);          // proj (analytic)
        if (n > MAXNORM) {
            float g = MAXNORM / n;
            #pragma unroll
            for (int j = 0; j < 8; j++) hv[j] *= g;
            h2 = MAXNORM * MAXNORM;
        }
        float pn = fmaxf(sqrtf(h2), MIN_NORM);         // logmap0 (analytic)
        float ls = artanh_clip(pn) / pn;

        __half2 o0 = __floats2half2_rn(hv[0] * ls, hv[1] * ls);
        __half2 o1 = __floats2half2_rn(hv[2] * ls, hv[3] * ls);
        __half2 o2 = __floats2half2_rn(hv[4] * ls, hv[5] * ls);
        __half2 o3 = __floats2half2_rn(hv[6] * ls, hv[7] * ls);
        uint2 ovA = make_uint2(*(uint32_t*)&o0, *(uint32_t*)&o1);
        uint2 ovB = make_uint2(*(uint32_t*)&o2, *(uint32_t*)&o3);
        *(uint2*)&g_xt[(size_t)row * DIM + c0]       = ovA;
        *(uint2*)&g_xt[(size_t)row * DIM + c0 + 128] = ovB;
    }
}

// ---------------- aggregation: warp-per-row, 4-edge MLP batches ----------
__global__ __launch_bounds__(256) void agg_k(float* __restrict__ out_opt, int n) {
    int w = threadIdx.x >> 5, lane = threadIdx.x & 31;
    int i = blockIdx.x * 8 + w;
    if (i >= n) return;
    int deg = min(g_cnt[i], BKT);
    const u64* bkt = &g_bkt[(size_t)i * BKT];

    float acc[8];
    #pragma unroll
    for (int j = 0; j < 8; j++) acc[j] = 0.0f;

    for (int base = 0; base < deg; base += 32) {
        int cnt = min(32, deg - base);
        int   myi = 0;
        float myw = 0.0f;
        if (lane < cnt) {
            u64 pair = bkt[base + lane];
            myi = (int)(uint32_t)pair;
            myw = __uint_as_float((uint32_t)(pair >> 32));
        }
        int e = 0;
        for (; e + 4 <= cnt; e += 4) {
            int   s0 = __shfl_sync(0xffffffffu, myi, e + 0);
            int   s1 = __shfl_sync(0xffffffffu, myi, e + 1);
            int   s2 = __shfl_sync(0xffffffffu, myi, e + 2);
            int   s3 = __shfl_sync(0xffffffffu, myi, e + 3);
            float w0 = __shfl_sync(0xffffffffu, myw, e + 0);
            float w1 = __shfl_sync(0xffffffffu, myw, e + 1);
            float w2 = __shfl_sync(0xffffffffu, myw, e + 2);
            float w3 = __shfl_sync(0xffffffffu, myw, e + 3);
            uint4 r0 = *(const uint4*)&g_xt[(size_t)s0 * DIM + lane * 8];
            uint4 r1 = *(const uint4*)&g_xt[(size_t)s1 * DIM + lane * 8];
            uint4 r2 = *(const uint4*)&g_xt[(size_t)s2 * DIM + lane * 8];
            uint4 r3 = *(const uint4*)&g_xt[(size_t)s3 * DIM + lane * 8];
            {
                float2 p0 = __half22float2(*(__half2*)&r0.x);
                float2 p1 = __half22float2(*(__half2*)&r0.y);
                float2 p2 = __half22float2(*(__half2*)&r0.z);
                float2 p3 = __half22float2(*(__half2*)&r0.w);
                acc[0] = fmaf(w0, p0.x, acc[0]); acc[1] = fmaf(w0, p0.y, acc[1]);
                acc[2] = fmaf(w0, p1.x, acc[2]); acc[3] = fmaf(w0, p1.y, acc[3]);
                acc[4] = fmaf(w0, p2.x, acc[4]); acc[5] = fmaf(w0, p2.y, acc[5]);
                acc[6] = fmaf(w0, p3.x, acc[6]); acc[7] = fmaf(w0, p3.y, acc[7]);
            }
            {
                float2 p0 = __half22float2(*(__half2*)&r1.x);
                float2 p1 = __half22float2(*(__half2*)&r1.y);
                float2 p2 = __half22float2(*(__half2*)&r1.z);
                float2 p3 = __half22float2(*(__half2*)&r1.w);
                acc[0] = fmaf(w1, p0.x, acc[0]); acc[1] = fmaf(w1, p0.y, acc[1]);
                acc[2] = fmaf(w1, p1.x, acc[2]); acc[3] = fmaf(w1, p1.y, acc[3]);
                acc[4] = fmaf(w1, p2.x, acc[4]); acc[5] = fmaf(w1, p2.y, acc[5]);
                acc[6] = fmaf(w1, p3.x, acc[6]); acc[7] = fmaf(w1, p3.y, acc[7]);
            }
            {
                float2 p0 = __half22float2(*(__half2*)&r2.x);
                float2 p1 = __half22float2(*(__half2*)&r2.y);
                float2 p2 = __half22float2(*(__half2*)&r2.z);
                float2 p3 = __half22float2(*(__half2*)&r2.w);
                acc[0] = fmaf(w2, p0.x, acc[0]); acc[1] = fmaf(w2, p0.y, acc[1]);
                acc[2] = fmaf(w2, p1.x, acc[2]); acc[3] = fmaf(w2, p1.y, acc[3]);
                acc[4] = fmaf(w2, p2.x, acc[4]); acc[5] = fmaf(w2, p2.y, acc[5]);
                acc[6] = fmaf(w2, p3.x, acc[6]); acc[7] = fmaf(w2, p3.y, acc[7]);
            }
            {
                float2 p0 = __half22float2(*(__half2*)&r3.x);
                float2 p1 = __half22float2(*(__half2*)&r3.y);
                float2 p2 = __half22float2(*(__half2*)&r3.z);
                float2 p3 = __half22float2(*(__half2*)&r3.w);
                acc[0] = fmaf(w3, p0.x, acc[0]); acc[1] = fmaf(w3, p0.y, acc[1]);
                acc[2] = fmaf(w3, p1.x, acc[2]); acc[3] = fmaf(w3, p1.y, acc[3]);
                acc[4] = fmaf(w3, p2.x, acc[4]); acc[5] = fmaf(w3, p2.y, acc[5]);
                acc[6] = fmaf(w3, p3.x, acc[6]); acc[7] = fmaf(w3, p3.y, acc[7]);
            }
        }
        for (; e < cnt; e++) {
            int   src = __shfl_sync(0xffffffffu, myi, e);
            float wt  = __shfl_sync(0xffffffffu, myw, e);
            uint4 raw = *(const uint4*)&g_xt[(size_t)src * DIM + lane * 8];
            float2 p0 = __half22float2(*(__half2*)&raw.x);
            float2 p1 = __half22float2(*(__half2*)&raw.y);
            float2 p2 = __half22float2(*(__half2*)&raw.z);
            float2 p3 = __half22float2(*(__half2*)&raw.w);
            acc[0] = fmaf(wt, p0.x, acc[0]); acc[1] = fmaf(wt, p0.y, acc[1]);
            acc[2] = fmaf(wt, p1.x, acc[2]); acc[3] = fmaf(wt, p1.y, acc[3]);
            acc[4] = fmaf(wt, p2.x, acc[4]); acc[5] = fmaf(wt, p2.y, acc[5]);
            acc[6] = fmaf(wt, p3.x, acc[6]); acc[7] = fmaf(wt, p3.y, acc[7]);
        }
    }

    // tail: 2 warp reductions, rest analytic
    float p = 0.0f;
    #pragma unroll
    for (int j = 0; j < 8; j++) p = fmaf(acc[j], acc[j], p);
    float s1 = wsum(p);                                // reduction #1
    float n1 = fmaxf(sqrtf(s1), MIN_NORM);
    float f1 = tanhf(n1) / n1;                         // expmap0
    float s  = s1 * f1 * f1;
    float n2 = fmaxf(sqrtf(s), MIN_NORM);              // proj (analytic)
    if (n2 > MAXNORM) { f1 *= MAXNORM / n2; s = MAXNORM * MAXNORM; }
    float n3 = fmaxf(sqrtf(s), MIN_NORM);              // logmap0 (analytic)
    float ls = artanh_clip(n3) / n3;
    float g1 = f1 * ls;
    #pragma unroll
    for (int j = 0; j < 8; j++) acc[j] = fmaxf(acc[j] * g1, 0.0f);  // relu

    p = 0.0f;
    #pragma unroll
    for (int j = 0; j < 8; j++) p = fmaf(acc[j], acc[j], p);
    float s5 = wsum(p);                                // reduction #2
    float n5 = fmaxf(sqrtf(s5), MIN_NORM);
    float f2 = tanhf(n5) / n5;                         // expmap0
    s = s5 * f2 * f2;
    float n6 = fmaxf(sqrtf(s), MIN_NORM);              // proj (analytic)
    if (n6 > MAXNORM) { f2 *= MAXNORM / n6; s = MAXNORM * MAXNORM; }
    #pragma unroll
    for (int j = 0; j < 8; j++) acc[j] *= f2;

    float4 o0 = make_float4(acc[0], acc[1], acc[2], acc[3]);
    float4 o1 = make_float4(acc[4], acc[5], acc[6], acc[7]);
    if (out_opt) {
        *(float4*)&out_opt[(size_t)i * DIM + lane * 8]     = o0;
        *(float4*)&out_opt[(size_t)i * DIM + lane * 8 + 4] = o1;
    } else {
        *(float4*)&g_h[(size_t)i * DIM + lane * 8]     = o0;
        *(float4*)&g_h[(size_t)i * DIM + lane * 8 + 4] = o1;
        if (lane == 0) g_x2[i] = s;
    }
}

// ---------------- launch ----------------
extern "C" void kernel_launch(void* const* d_in, const int* in_sizes, int n_in,
                              void* d_out, int out_size) {
    const float* x    = (const float*)d_in[0];
    const float* W1   = (const float*)d_in[1];
    const float* b1   = (const float*)d_in[2];
    const float* W2   = (const float*)d_in[3];
    const float* b2   = (const float*)d_in[4];
    const float* ew   = (const float*)d_in[5];
    const int*   esrc = (const int*)d_in[6];
    const int*   edst = (const int*)d_in[7];
    float*       out  = (float*)d_out;

    int n = in_sizes[0] / DIM;   // 10000
    int E = in_sizes[5];         // 320000

    // Fork the bucket build onto a side stream; overlap with init + gemm1.
    // Streams/events created only on non-replay calls; never destroyed here.
    cudaStream_t s2;
    cudaEvent_t e1, e2;
    cudaStreamCreateWithFlags(&s2, cudaStreamNonBlocking);
    cudaEventCreateWithFlags(&e1, cudaEventDisableTiming);
    cudaEventCreateWithFlags(&e2, cudaEventDisableTiming);

    // kernel-launch order: init(0), zero(1), fillb(2), gemm1(3), agg1(4),
    // gemm2(5) <- ncu -s 5 profiles the GEMM, agg2(6)
    init_k<<<(n + 2 + 7) / 8, 256>>>(x, b1, b2, n);

    cudaEventRecord(e1, 0);
    cudaStreamWaitEvent(s2, e1, 0);
    zero_k<<<(n + 255) / 256, 256, 0, s2>>>(n);
    fillb_k<<<(E + 255) / 256, 256, 0, s2>>>(esrc, edst, ew, E);
    cudaEventRecord(e2, s2);

    int gblocks = (n + GBM - 1) / GBM;   // 313

    gemm_fused_k<<<gblocks, 256>>>(W1, 0, n);

    cudaStreamWaitEvent(0, e2, 0);
    agg_k<<<(n + 7) / 8, 256>>>(nullptr, n);

    gemm_fused_k<<<gblocks, 256>>>(W2, 1, n);
    agg_k<<<(n + 7) / 8, 256>>>(out, n);
}

// round 14
// speedup vs baseline: 1.9156x; 1.0640x over previous
#include <cuda_runtime.h>
#include <cuda_fp16.h>
#include <cstdint>

#define N_NODES 10000
#define DIM     256
#define E_MAX   320000
#define BKT     96            // bucket capacity per node (Poisson(32): mean+11σ)

#define MIN_NORM 1e-15f
#define MAXNORM  0.996f      // (1 - 4e-3)/sqrt(c), c = 1

// ---------------- device scratch (no allocations allowed) ----------------
typedef unsigned long long u64;

__device__ float   g_h  [N_NODES * DIM];    // current hyperbolic features (fp32)
__device__ __half  g_xt [N_NODES * DIM];    // tangent features (fp16)
__device__ float   g_x2 [N_NODES];          // sumsq of each g_h row
__device__ int     g_cnt[N_NODES];          // per-node degree counter
__device__ u64     g_bkt[N_NODES * BKT];    // packed (src, weight) pairs
__device__ float   g_bias[2][DIM];
__device__ float   g_by2[2];                // sumsq of hyp_bias per layer

// ---------------- packed f32x2 helpers (sm_100+ PTX) ------
#define FMA2(d, a, b, c) \
    asm("fma.rn.f32x2 %0, %1, %2, %3;" : "=l"(d) : "l"(a), "l"(b), "l"(c))

__device__ __forceinline__ u64 pack_dup(float a) {
    u64 r;
    asm("mov.b64 %0, {%1, %1};" : "=l"(r) : "r"(__float_as_uint(a)));
    return r;
}
__device__ __forceinline__ u64 pack2(float lo, float hi) {
    u64 r;
    asm("mov.b64 %0, {%1, %2};" : "=l"(r) : "r"(__float_as_uint(lo)), "r"(__float_as_uint(hi)));
    return r;
}
__device__ __forceinline__ float lo_f(u64 v) { return __uint_as_float((uint32_t)v); }
__device__ __forceinline__ float hi_f(u64 v) { return __uint_as_float((uint32_t)(v >> 32)); }

// ---------------- math helpers ----------------
__device__ __forceinline__ float artanh_clip(float x) {
    x = fminf(fmaxf(x, -1.0f + 1e-7f), 1.0f - 1e-7f);
    return atanhf(x);
}

__device__ __forceinline__ float wsum(float v) {
    #pragma unroll
    for (int o = 16; o > 0; o >>= 1) v += __shfl_xor_sync(0xffffffffu, v, o);
    return v;
}

// ---------------- bucket build ----------------
__global__ void zero_k(int n) {
    int i = blockIdx.x * blockDim.x + threadIdx.x;
    if (i < n) g_cnt[i] = 0;
}

__global__ void fillb_k(const int* __restrict__ src, const int* __restrict__ dst,
                        const float* __restrict__ w, int E) {
    int e = blockIdx.x * blockDim.x + threadIdx.x;
    if (e < E) {
        int d = dst[e];
        int slot = atomicAdd(&g_cnt[d], 1);
        if (slot < BKT) {
            u64 pair = (u64)(uint32_t)src[e] | ((u64)__float_as_uint(w[e]) << 32);
            g_bkt[(size_t)d * BKT + slot] = pair;
        }
    }
}

// ---------------- init: warp-per-row, barrier-free ----------
__global__ void init_k(const float* __restrict__ x,
                       const float* __restrict__ b1,
                       const float* __restrict__ b2, int n) {
    int w = threadIdx.x >> 5, lane = threadIdx.x & 31;
    int i = blockIdx.x * 8 + w;
    if (i >= n + 2) return;
    bool is_bias = (i >= n);
    const float* srcv = is_bias ? ((i == n) ? b1 : b2) : x + (size_t)i * DIM;

    float4 v0 = *(const float4*)&srcv[lane * 8];
    float4 v1 = *(const float4*)&srcv[lane * 8 + 4];

    float p = v0.x * v0.x + v0.y * v0.y + v0.z * v0.z + v0.w * v0.w
            + v1.x * v1.x + v1.y * v1.y + v1.z * v1.z + v1.w * v1.w;
    float s1 = wsum(p);
    float nn = fmaxf(sqrtf(s1), MIN_NORM);
    float f  = tanhf(nn) / nn;                 // expmap0
    float s  = s1 * f * f;
    float n2 = fmaxf(sqrtf(s), MIN_NORM);      // proj (analytic)
    if (n2 > MAXNORM) { f *= MAXNORM / n2; s = MAXNORM * MAXNORM; }
    v0.x *= f; v0.y *= f; v0.z *= f; v0.w *= f;
    v1.x *= f; v1.y *= f; v1.z *= f; v1.w *= f;

    if (is_bias) {
        int L = i - n;
        *(float4*)&g_bias[L][lane * 8]     = v0;
        *(float4*)&g_bias[L][lane * 8 + 4] = v1;
        if (lane == 0) g_by2[L] = s;
    } else {
        *(float4*)&g_h[(size_t)i * DIM + lane * 8]     = v0;
        *(float4*)&g_h[(size_t)i * DIM + lane * 8 + 4] = v1;
        if (lane == 0) g_x2[i] = s;
    }
}

// ---------------- fused GEMM (f32x2) + HypLinear tail -> g_xt ----------
// mx = h @ W^T. BM=64 rows/CTA; 8 warps x 8 rows (doubles B smem reuse vs
// 4 rows/warp); grid=157 <= 296 capacity at 2 CTAs/SM -> single wave.
// Lane owns cols {4*lane + 128*j + c}: B read = 2x LDS.128, 16-byte lane
// stride (conflict-free). A read = 2x LDS.128 broadcast (8 row values).
#define GBM 64
#define GBK 16
#define AP  68                 // 68*4 = 272 B row stride (16B aligned)
#define BP  260                // 260*4 = 1040 B row stride (16B aligned)

__global__ __launch_bounds__(256, 2) void gemm_fused_k(const float* __restrict__ W,
                                                       int layer, int M) {
    __shared__ float As[GBK][AP];
    __shared__ float Bs[GBK][BP];
    int tid = threadIdx.x;
    int bm  = blockIdx.x * GBM;
    int lane = tid & 31;
    int ty   = tid >> 5;       // warp 0..7: rows bm + ty*8 .. +7

    u64 acc[8][4];
    #pragma unroll
    for (int i = 0; i < 8; i++)
        #pragma unroll
        for (int j = 0; j < 4; j++) acc[i][j] = 0ull;

    int a_r = tid >> 2;            // 0..63
    int a_k = (tid & 3) << 2;      // 0,4,8,12
    int b_j = tid >> 2;            // 0..63 (+64q)
    int b_k = (tid & 3) << 2;      // 0,4,8,12

    for (int k0 = 0; k0 < DIM; k0 += GBK) {
        {
            int r = bm + a_r;
            float4 v = make_float4(0.f, 0.f, 0.f, 0.f);
            if (r < M) v = *(const float4*)&g_h[(size_t)r * DIM + k0 + a_k];
            As[a_k + 0][a_r] = v.x;
            As[a_k + 1][a_r] = v.y;
            As[a_k + 2][a_r] = v.z;
            As[a_k + 3][a_r] = v.w;
        }
        #pragma unroll
        for (int q = 0; q < 4; q++) {
            int j = b_j + 64 * q;
            float4 v = *(const float4*)&W[(size_t)j * DIM + k0 + b_k];
            Bs[b_k + 0][j] = v.x;
            Bs[b_k + 1][j] = v.y;
            Bs[b_k + 2][j] = v.z;
            Bs[b_k + 3][j] = v.w;
        }
        __syncthreads();
        #pragma unroll
        for (int k = 0; k < GBK; k++) {
            float4 aA = *(const float4*)&As[k][ty * 8];            // broadcast
            float4 aB = *(const float4*)&As[k][ty * 8 + 4];        // broadcast
            float4 bA = *(const float4*)&Bs[k][4 * lane];          // 16B stride
            float4 bB = *(const float4*)&Bs[k][4 * lane + 128];    // 16B stride
            u64 bp0 = pack2(bA.x, bA.y);
            u64 bp1 = pack2(bA.z, bA.w);
            u64 bp2 = pack2(bB.x, bB.y);
            u64 bp3 = pack2(bB.z, bB.w);
            u64 ad[8];
            ad[0] = pack_dup(aA.x); ad[1] = pack_dup(aA.y);
            ad[2] = pack_dup(aA.z); ad[3] = pack_dup(aA.w);
            ad[4] = pack_dup(aB.x); ad[5] = pack_dup(aB.y);
            ad[6] = pack_dup(aB.z); ad[7] = pack_dup(aB.w);
            #pragma unroll
            for (int i = 0; i < 8; i++) {
                FMA2(acc[i][0], ad[i], bp0, acc[i][0]);
                FMA2(acc[i][1], ad[i], bp1, acc[i][1]);
                FMA2(acc[i][2], ad[i], bp2, acc[i][2]);
                FMA2(acc[i][3], ad[i], bp3, acc[i][3]);
            }
        }
        __syncthreads();
    }

    // ---- epilogue: 2 warp reductions per row, rest analytic ----
    // pair j: j=0 -> cols 4L+0,1; j=1 -> 4L+2,3; j=2 -> 4L+128,129; j=3 -> 4L+130,131
    int c0 = 4 * lane;
    float4 yv0 = *(const float4*)&g_bias[layer][c0];
    float4 yv1 = *(const float4*)&g_bias[layer][c0 + 128];
    float y[8] = {yv0.x, yv0.y, yv0.z, yv0.w, yv1.x, yv1.y, yv1.z, yv1.w};
    float y2 = g_by2[layer];

    #pragma unroll
    for (int i = 0; i < 8; i++) {
        int row = bm + ty * 8 + i;
        if (row >= M) continue;

        float mxv[8];
        #pragma unroll
        for (int j = 0; j < 4; j++) {
            mxv[2 * j]     = lo_f(acc[i][j]);
            mxv[2 * j + 1] = hi_f(acc[i][j]);
        }

        float msq = 0.0f;
        #pragma unroll
        for (int j = 0; j < 8; j++) msq = fmaf(mxv[j], mxv[j], msq);
        float m2s = wsum(msq);                         // reduction #1

        float res[8];
        float x2;
        if (m2s == 0.0f) {
            #pragma unroll
            for (int j = 0; j < 8; j++) res[j] = 0.0f;
            x2 = 0.0f;
        } else {
            float x_norm = fmaxf(sqrtf(g_x2[row]), MIN_NORM);
            float mxn = fmaxf(sqrtf(m2s), MIN_NORM);
            float sc = tanhf(mxn / x_norm * artanh_clip(x_norm)) / mxn;
            #pragma unroll
            for (int j = 0; j < 8; j++) res[j] = mxv[j] * sc;
            x2 = m2s * sc * sc;
            float n = fmaxf(sqrtf(x2), MIN_NORM);      // proj (analytic)
            if (n > MAXNORM) {
                float g = MAXNORM / n;
                #pragma unroll
                for (int j = 0; j < 8; j++) res[j] *= g;
                x2 = MAXNORM * MAXNORM;
            }
        }

        float pxy = 0.0f;
        #pragma unroll
        for (int j = 0; j < 8; j++) pxy = fmaf(res[j], y[j], pxy);
        float xy = wsum(pxy);                          // reduction #2

        float ca  = 1.0f + 2.0f * xy + y2;
        float cb  = 1.0f - x2;
        float den = fmaxf(1.0f + 2.0f * xy + x2 * y2, MIN_NORM);
        float inv = 1.0f / den;
        float hv[8];
        #pragma unroll
        for (int j = 0; j < 8; j++) hv[j] = (ca * res[j] + cb * y[j]) * inv;
        float h2 = inv * inv * (ca * ca * x2 + 2.0f * ca * cb * xy + cb * cb * y2);

        float n = fmaxf(sqrtf(h2), MIN_NORM);          // proj (analytic)
        if (n > MAXNORM) {
            float g = MAXNORM / n;
            #pragma unroll
            for (int j = 0; j < 8; j++) hv[j] *= g;
            h2 = MAXNORM * MAXNORM;
        }
        float pn = fmaxf(sqrtf(h2), MIN_NORM);         // logmap0 (analytic)
        float ls = artanh_clip(pn) / pn;

        __half2 o0 = __floats2half2_rn(hv[0] * ls, hv[1] * ls);
        __half2 o1 = __floats2half2_rn(hv[2] * ls, hv[3] * ls);
        __half2 o2 = __floats2half2_rn(hv[4] * ls, hv[5] * ls);
        __half2 o3 = __floats2half2_rn(hv[6] * ls, hv[7] * ls);
        uint2 ovA = make_uint2(*(uint32_t*)&o0, *(uint32_t*)&o1);
        uint2 ovB = make_uint2(*(uint32_t*)&o2, *(uint32_t*)&o3);
        *(uint2*)&g_xt[(size_t)row * DIM + c0]       = ovA;
        *(uint2*)&g_xt[(size_t)row * DIM + c0 + 128] = ovB;
    }
}

// ---------------- aggregation: warp-per-row, 4-edge MLP batches ----------
__global__ __launch_bounds__(256) void agg_k(float* __restrict__ out_opt, int n) {
    int w = threadIdx.x >> 5, lane = threadIdx.x & 31;
    int i = blockIdx.x * 8 + w;
    if (i >= n) return;
    int deg = min(g_cnt[i], BKT);
    const u64* bkt = &g_bkt[(size_t)i * BKT];

    float acc[8];
    #pragma unroll
    for (int j = 0; j < 8; j++) acc[j] = 0.0f;

    for (int base = 0; base < deg; base += 32) {
        int cnt = min(32, deg - base);
        int   myi = 0;
        float myw = 0.0f;
        if (lane < cnt) {
            u64 pair = bkt[base + lane];
            myi = (int)(uint32_t)pair;
            myw = __uint_as_float((uint32_t)(pair >> 32));
        }
        int e = 0;
        for (; e + 4 <= cnt; e += 4) {
            int   s0 = __shfl_sync(0xffffffffu, myi, e + 0);
            int   s1 = __shfl_sync(0xffffffffu, myi, e + 1);
            int   s2 = __shfl_sync(0xffffffffu, myi, e + 2);
            int   s3 = __shfl_sync(0xffffffffu, myi, e + 3);
            float w0 = __shfl_sync(0xffffffffu, myw, e + 0);
            float w1 = __shfl_sync(0xffffffffu, myw, e + 1);
            float w2 = __shfl_sync(0xffffffffu, myw, e + 2);
            float w3 = __shfl_sync(0xffffffffu, myw, e + 3);
            uint4 r0 = *(const uint4*)&g_xt[(size_t)s0 * DIM + lane * 8];
            uint4 r1 = *(const uint4*)&g_xt[(size_t)s1 * DIM + lane * 8];
            uint4 r2 = *(const uint4*)&g_xt[(size_t)s2 * DIM + lane * 8];
            uint4 r3 = *(const uint4*)&g_xt[(size_t)s3 * DIM + lane * 8];
            {
                float2 p0 = __half22float2(*(__half2*)&r0.x);
                float2 p1 = __half22float2(*(__half2*)&r0.y);
                float2 p2 = __half22float2(*(__half2*)&r0.z);
                float2 p3 = __half22float2(*(__half2*)&r0.w);
                acc[0] = fmaf(w0, p0.x, acc[0]); acc[1] = fmaf(w0, p0.y, acc[1]);
                acc[2] = fmaf(w0, p1.x, acc[2]); acc[3] = fmaf(w0, p1.y, acc[3]);
                acc[4] = fmaf(w0, p2.x, acc[4]); acc[5] = fmaf(w0, p2.y, acc[5]);
                acc[6] = fmaf(w0, p3.x, acc[6]); acc[7] = fmaf(w0, p3.y, acc[7]);
            }
            {
                float2 p0 = __half22float2(*(__half2*)&r1.x);
                float2 p1 = __half22float2(*(__half2*)&r1.y);
                float2 p2 = __half22float2(*(__half2*)&r1.z);
                float2 p3 = __half22float2(*(__half2*)&r1.w);
                acc[0] = fmaf(w1, p0.x, acc[0]); acc[1] = fmaf(w1, p0.y, acc[1]);
                acc[2] = fmaf(w1, p1.x, acc[2]); acc[3] = fmaf(w1, p1.y, acc[3]);
                acc[4] = fmaf(w1, p2.x, acc[4]); acc[5] = fmaf(w1, p2.y, acc[5]);
                acc[6] = fmaf(w1, p3.x, acc[6]); acc[7] = fmaf(w1, p3.y, acc[7]);
            }
            {
                float2 p0 = __half22float2(*(__half2*)&r2.x);
                float2 p1 = __half22float2(*(__half2*)&r2.y);
                float2 p2 = __half22float2(*(__half2*)&r2.z);
                float2 p3 = __half22float2(*(__half2*)&r2.w);
                acc[0] = fmaf(w2, p0.x, acc[0]); acc[1] = fmaf(w2, p0.y, acc[1]);
                acc[2] = fmaf(w2, p1.x, acc[2]); acc[3] = fmaf(w2, p1.y, acc[3]);
                acc[4] = fmaf(w2, p2.x, acc[4]); acc[5] = fmaf(w2, p2.y, acc[5]);
                acc[6] = fmaf(w2, p3.x, acc[6]); acc[7] = fmaf(w2, p3.y, acc[7]);
            }
            {
                float2 p0 = __half22float2(*(__half2*)&r3.x);
                float2 p1 = __half22float2(*(__half2*)&r3.y);
                float2 p2 = __half22float2(*(__half2*)&r3.z);
                float2 p3 = __half22float2(*(__half2*)&r3.w);
                acc[0] = fmaf(w3, p0.x, acc[0]); acc[1] = fmaf(w3, p0.y, acc[1]);
                acc[2] = fmaf(w3, p1.x, acc[2]); acc[3] = fmaf(w3, p1.y, acc[3]);
                acc[4] = fmaf(w3, p2.x, acc[4]); acc[5] = fmaf(w3, p2.y, acc[5]);
                acc[6] = fmaf(w3, p3.x, acc[6]); acc[7] = fmaf(w3, p3.y, acc[7]);
            }
        }
        for (; e < cnt; e++) {
            int   src = __shfl_sync(0xffffffffu, myi, e);
            float wt  = __shfl_sync(0xffffffffu, myw, e);
            uint4 raw = *(const uint4*)&g_xt[(size_t)src * DIM + lane * 8];
            float2 p0 = __half22float2(*(__half2*)&raw.x);
            float2 p1 = __half22float2(*(__half2*)&raw.y);
            float2 p2 = __half22float2(*(__half2*)&raw.z);
            float2 p3 = __half22float2(*(__half2*)&raw.w);
            acc[0] = fmaf(wt, p0.x, acc[0]); acc[1] = fmaf(wt, p0.y, acc[1]);
            acc[2] = fmaf(wt, p1.x, acc[2]); acc[3] = fmaf(wt, p1.y, acc[3]);
            acc[4] = fmaf(wt, p2.x, acc[4]); acc[5] = fmaf(wt, p2.y, acc[5]);
            acc[6] = fmaf(wt, p3.x, acc[6]); acc[7] = fmaf(wt, p3.y, acc[7]);
        }
    }

    // tail: 2 warp reductions, rest analytic
    float p = 0.0f;
    #pragma unroll
    for (int j = 0; j < 8; j++) p = fmaf(acc[j], acc[j], p);
    float s1 = wsum(p);                                // reduction #1
    float n1 = fmaxf(sqrtf(s1), MIN_NORM);
    float f1 = tanhf(n1) / n1;                         // expmap0
    float s  = s1 * f1 * f1;
    float n2 = fmaxf(sqrtf(s), MIN_NORM);              // proj (analytic)
    if (n2 > MAXNORM) { f1 *= MAXNORM / n2; s = MAXNORM * MAXNORM; }
    float n3 = fmaxf(sqrtf(s), MIN_NORM);              // logmap0 (analytic)
    float ls = artanh_clip(n3) / n3;
    float g1 = f1 * ls;
    #pragma unroll
    for (int j = 0; j < 8; j++) acc[j] = fmaxf(acc[j] * g1, 0.0f);  // relu

    p = 0.0f;
    #pragma unroll
    for (int j = 0; j < 8; j++) p = fmaf(acc[j], acc[j], p);
    float s5 = wsum(p);                                // reduction #2
    float n5 = fmaxf(sqrtf(s5), MIN_NORM);
    float f2 = tanhf(n5) / n5;                         // expmap0
    s = s5 * f2 * f2;
    float n6 = fmaxf(sqrtf(s), MIN_NORM);              // proj (analytic)
    if (n6 > MAXNORM) { f2 *= MAXNORM / n6; s = MAXNORM * MAXNORM; }
    #pragma unroll
    for (int j = 0; j < 8; j++) acc[j] *= f2;

    float4 o0 = make_float4(acc[0], acc[1], acc[2], acc[3]);
    float4 o1 = make_float4(acc[4], acc[5], acc[6], acc[7]);
    if (out_opt) {
        *(float4*)&out_opt[(size_t)i * DIM + lane * 8]     = o0;
        *(float4*)&out_opt[(size_t)i * DIM + lane * 8 + 4] = o1;
    } else {
        *(float4*)&g_h[(size_t)i * DIM + lane * 8]     = o0;
        *(float4*)&g_h[(size_t)i * DIM + lane * 8 + 4] = o1;
        if (lane == 0) g_x2[i] = s;
    }
}

// ---------------- launch ----------------
extern "C" void kernel_launch(void* const* d_in, const int* in_sizes, int n_in,
                              void* d_out, int out_size) {
    const float* x    = (const float*)d_in[0];
    const float* W1   = (const float*)d_in[1];
    const float* b1   = (const float*)d_in[2];
    const float* W2   = (const float*)d_in[3];
    const float* b2   = (const float*)d_in[4];
    const float* ew   = (const float*)d_in[5];
    const int*   esrc = (const int*)d_in[6];
    const int*   edst = (const int*)d_in[7];
    float*       out  = (float*)d_out;

    int n = in_sizes[0] / DIM;   // 10000
    int E = in_sizes[5];         // 320000

    // Fork the bucket build onto a side stream; overlap with init + gemm1.
    // Streams/events created only on non-replay calls; never destroyed here.
    cudaStream_t s2;
    cudaEvent_t e1, e2;
    cudaStreamCreateWithFlags(&s2, cudaStreamNonBlocking);
    cudaEventCreateWithFlags(&e1, cudaEventDisableTiming);
    cudaEventCreateWithFlags(&e2, cudaEventDisableTiming);

    // kernel-launch order: init(0), zero(1), fillb(2), gemm1(3), agg1(4),
    // gemm2(5) <- ncu -s 5 profiles the GEMM, agg2(6)
    init_k<<<(n + 2 + 7) / 8, 256>>>(x, b1, b2, n);

    cudaEventRecord(e1, 0);
    cudaStreamWaitEvent(s2, e1, 0);
    zero_k<<<(n + 255) / 256, 256, 0, s2>>>(n);
    fillb_k<<<(E + 255) / 256, 256, 0, s2>>>(esrc, edst, ew, E);
    cudaEventRecord(e2, s2);

    int gblocks = (n + GBM - 1) / GBM;   // 157

    gemm_fused_k<<<gblocks, 256>>>(W1, 0, n);

    cudaStreamWaitEvent(0, e2, 0);
    agg_k<<<(n + 7) / 8, 256>>>(nullptr, n);

    gemm_fused_k<<<gblocks, 256>>>(W2, 1, n);
    agg_k<<<(n + 7) / 8, 256>>>(out, n);
}

// round 15
// speedup vs baseline: 2.1409x; 1.1176x over previous
#include <cuda_runtime.h>
#include <cuda_fp16.h>
#include <cstdint>

#define N_NODES 10000
#define DIM     256
#define E_MAX   320000
#define BKT     96            // bucket capacity per node (Poisson(32): mean+11σ)

#define MIN_NORM 1e-15f
#define MAXNORM  0.996f      // (1 - 4e-3)/sqrt(c), c = 1

// ---------------- device scratch (no allocations allowed) ----------------
typedef unsigned long long u64;

__device__ float   g_h  [N_NODES * DIM];    // current hyperbolic features (fp32)
__device__ __half  g_xt [N_NODES * DIM];    // tangent features (fp16)
__device__ float   g_x2 [N_NODES];          // sumsq of each g_h row
__device__ int     g_cnt[N_NODES];          // per-node degree counter
__device__ u64     g_bkt[N_NODES * BKT];    // packed (src, weight) pairs
__device__ float   g_bias[2][DIM];
__device__ float   g_by2[2];                // sumsq of hyp_bias per layer

// ---------------- packed f32x2 helpers (sm_100+ PTX) ------
#define FMA2(d, a, b, c) \
    asm("fma.rn.f32x2 %0, %1, %2, %3;" : "=l"(d) : "l"(a), "l"(b), "l"(c))

__device__ __forceinline__ u64 pack_dup(float a) {
    u64 r;
    asm("mov.b64 %0, {%1, %1};" : "=l"(r) : "r"(__float_as_uint(a)));
    return r;
}
__device__ __forceinline__ u64 pack2(float lo, float hi) {
    u64 r;
    asm("mov.b64 %0, {%1, %2};" : "=l"(r) : "r"(__float_as_uint(lo)), "r"(__float_as_uint(hi)));
    return r;
}
__device__ __forceinline__ float lo_f(u64 v) { return __uint_as_float((uint32_t)v); }
__device__ __forceinline__ float hi_f(u64 v) { return __uint_as_float((uint32_t)(v >> 32)); }

// ---------------- math helpers ----------------
__device__ __forceinline__ float artanh_clip(float x) {
    x = fminf(fmaxf(x, -1.0f + 1e-7f), 1.0f - 1e-7f);
    return atanhf(x);
}

__device__ __forceinline__ float wsum(float v) {
    #pragma unroll
    for (int o = 16; o > 0; o >>= 1) v += __shfl_xor_sync(0xffffffffu, v, o);
    return v;
}

// ---------------- bucket build ----------------
__global__ void zero_k(int n) {
    int i = blockIdx.x * blockDim.x + threadIdx.x;
    if (i < n) g_cnt[i] = 0;
}

__global__ void fillb_k(const int* __restrict__ src, const int* __restrict__ dst,
                        const float* __restrict__ w, int E) {
    int e = blockIdx.x * blockDim.x + threadIdx.x;
    if (e < E) {
        int d = dst[e];
        int slot = atomicAdd(&g_cnt[d], 1);
        if (slot < BKT) {
            u64 pair = (u64)(uint32_t)src[e] | ((u64)__float_as_uint(w[e]) << 32);
            g_bkt[(size_t)d * BKT + slot] = pair;
        }
    }
}

// ---------------- init: warp-per-row, barrier-free ----------
__global__ void init_k(const float* __restrict__ x,
                       const float* __restrict__ b1,
                       const float* __restrict__ b2, int n) {
    int w = threadIdx.x >> 5, lane = threadIdx.x & 31;
    int i = blockIdx.x * 8 + w;
    if (i >= n + 2) return;
    bool is_bias = (i >= n);
    const float* srcv = is_bias ? ((i == n) ? b1 : b2) : x + (size_t)i * DIM;

    float4 v0 = *(const float4*)&srcv[lane * 8];
    float4 v1 = *(const float4*)&srcv[lane * 8 + 4];

    float p = v0.x * v0.x + v0.y * v0.y + v0.z * v0.z + v0.w * v0.w
            + v1.x * v1.x + v1.y * v1.y + v1.z * v1.z + v1.w * v1.w;
    float s1 = wsum(p);
    float nn = fmaxf(sqrtf(s1), MIN_NORM);
    float f  = tanhf(nn) / nn;                 // expmap0
    float s  = s1 * f * f;
    float n2 = fmaxf(sqrtf(s), MIN_NORM);      // proj (analytic)
    if (n2 > MAXNORM) { f *= MAXNORM / n2; s = MAXNORM * MAXNORM; }
    v0.x *= f; v0.y *= f; v0.z *= f; v0.w *= f;
    v1.x *= f; v1.y *= f; v1.z *= f; v1.w *= f;

    if (is_bias) {
        int L = i - n;
        *(float4*)&g_bias[L][lane * 8]     = v0;
        *(float4*)&g_bias[L][lane * 8 + 4] = v1;
        if (lane == 0) g_by2[L] = s;
    } else {
        *(float4*)&g_h[(size_t)i * DIM + lane * 8]     = v0;
        *(float4*)&g_h[(size_t)i * DIM + lane * 8 + 4] = v1;
        if (lane == 0) g_x2[i] = s;
    }
}

// ---------------- fused GEMM (f32x2) + HypLinear tail -> g_xt ----------
// mx = h @ W^T. BM=72 rows/CTA -> grid = 139 <= 148 SMs: ONE balanced wave
// (R14 proved 2x per-CTA engine but lost it all to a 157-CTA tail wave).
// 8 warps x 9 rows. A tile stored with 12-float warp stride so the 9 row
// values read as 2x LDS.128 + 1x LDS.32, all warp-uniform broadcasts.
// Lane owns cols {4*lane + 128*j + c}: B read = 2x LDS.128, 16-byte lane
// stride (conflict-free).
#define GBM 72
#define RPW 9                  // rows per warp
#define WST 12                 // A-tile warp stride (floats); 48 B = 16B-aligned
#define GBK 16
#define AP  100                // 8*12 + 4 pad
#define BP  260                // 260*4 = 1040 B row stride (16B aligned)

__global__ __launch_bounds__(256) void gemm_fused_k(const float* __restrict__ W,
                                                    int layer, int M) {
    __shared__ float As[GBK][AP];
    __shared__ float Bs[GBK][BP];
    int tid = threadIdx.x;
    int bm  = blockIdx.x * GBM;
    int lane = tid & 31;
    int ty   = tid >> 5;       // warp 0..7: rows bm + ty*9 .. +8

    u64 acc[RPW][4];
    #pragma unroll
    for (int i = 0; i < RPW; i++)
        #pragma unroll
        for (int j = 0; j < 4; j++) acc[i][j] = 0ull;

    int b_j = tid >> 2;            // 0..63 (+64q)
    int b_k = (tid & 3) << 2;      // 0,4,8,12

    for (int k0 = 0; k0 < DIM; k0 += GBK) {
        // A tile: 72 rows x 16 k = 288 float4 loads over 256 threads
        #pragma unroll
        for (int u = 0; u < 2; u++) {
            int idx = tid + u * 256;
            if (idx < (GBM * GBK) / 4) {
                int r = idx >> 2;              // 0..71
                int kk = (idx & 3) << 2;       // 0,4,8,12
                int rr = bm + r;
                float4 v = make_float4(0.f, 0.f, 0.f, 0.f);
                if (rr < M) v = *(const float4*)&g_h[(size_t)rr * DIM + k0 + kk];
                int cm = (r / RPW) * WST + (r % RPW);
                As[kk + 0][cm] = v.x;
                As[kk + 1][cm] = v.y;
                As[kk + 2][cm] = v.z;
                As[kk + 3][cm] = v.w;
            }
        }
        // B tile: 256 cols x 16 k
        #pragma unroll
        for (int q = 0; q < 4; q++) {
            int j = b_j + 64 * q;
            float4 v = *(const float4*)&W[(size_t)j * DIM + k0 + b_k];
            Bs[b_k + 0][j] = v.x;
            Bs[b_k + 1][j] = v.y;
            Bs[b_k + 2][j] = v.z;
            Bs[b_k + 3][j] = v.w;
        }
        __syncthreads();
        #pragma unroll
        for (int k = 0; k < GBK; k++) {
            float4 aA = *(const float4*)&As[k][ty * WST];          // broadcast
            float4 aB = *(const float4*)&As[k][ty * WST + 4];      // broadcast
            float  a8 = As[k][ty * WST + 8];                        // broadcast
            float4 bA = *(const float4*)&Bs[k][4 * lane];          // 16B stride
            float4 bB = *(const float4*)&Bs[k][4 * lane + 128];    // 16B stride
            u64 bp0 = pack2(bA.x, bA.y);
            u64 bp1 = pack2(bA.z, bA.w);
            u64 bp2 = pack2(bB.x, bB.y);
            u64 bp3 = pack2(bB.z, bB.w);
            u64 ad[RPW];
            ad[0] = pack_dup(aA.x); ad[1] = pack_dup(aA.y);
            ad[2] = pack_dup(aA.z); ad[3] = pack_dup(aA.w);
            ad[4] = pack_dup(aB.x); ad[5] = pack_dup(aB.y);
            ad[6] = pack_dup(aB.z); ad[7] = pack_dup(aB.w);
            ad[8] = pack_dup(a8);
            #pragma unroll
            for (int i = 0; i < RPW; i++) {
                FMA2(acc[i][0], ad[i], bp0, acc[i][0]);
                FMA2(acc[i][1], ad[i], bp1, acc[i][1]);
                FMA2(acc[i][2], ad[i], bp2, acc[i][2]);
                FMA2(acc[i][3], ad[i], bp3, acc[i][3]);
            }
        }
        __syncthreads();
    }

    // ---- epilogue: 2 warp reductions per row, rest analytic ----
    int c0 = 4 * lane;
    float4 yv0 = *(const float4*)&g_bias[layer][c0];
    float4 yv1 = *(const float4*)&g_bias[layer][c0 + 128];
    float y[8] = {yv0.x, yv0.y, yv0.z, yv0.w, yv1.x, yv1.y, yv1.z, yv1.w};
    float y2 = g_by2[layer];

    #pragma unroll
    for (int i = 0; i < RPW; i++) {
        int row = bm + ty * RPW + i;
        if (row >= M) continue;

        float mxv[8];
        #pragma unroll
        for (int j = 0; j < 4; j++) {
            mxv[2 * j]     = lo_f(acc[i][j]);
            mxv[2 * j + 1] = hi_f(acc[i][j]);
        }

        float msq = 0.0f;
        #pragma unroll
        for (int j = 0; j < 8; j++) msq = fmaf(mxv[j], mxv[j], msq);
        float m2s = wsum(msq);                         // reduction #1

        float res[8];
        float x2;
        if (m2s == 0.0f) {
            #pragma unroll
            for (int j = 0; j < 8; j++) res[j] = 0.0f;
            x2 = 0.0f;
        } else {
            float x_norm = fmaxf(sqrtf(g_x2[row]), MIN_NORM);
            float mxn = fmaxf(sqrtf(m2s), MIN_NORM);
            float sc = tanhf(mxn / x_norm * artanh_clip(x_norm)) / mxn;
            #pragma unroll
            for (int j = 0; j < 8; j++) res[j] = mxv[j] * sc;
            x2 = m2s * sc * sc;
            float n = fmaxf(sqrtf(x2), MIN_NORM);      // proj (analytic)
            if (n > MAXNORM) {
                float g = MAXNORM / n;
                #pragma unroll
                for (int j = 0; j < 8; j++) res[j] *= g;
                x2 = MAXNORM * MAXNORM;
            }
        }

        float pxy = 0.0f;
        #pragma unroll
        for (int j = 0; j < 8; j++) pxy = fmaf(res[j], y[j], pxy);
        float xy = wsum(pxy);                          // reduction #2

        float ca  = 1.0f + 2.0f * xy + y2;
        float cb  = 1.0f - x2;
        float den = fmaxf(1.0f + 2.0f * xy + x2 * y2, MIN_NORM);
        float inv = 1.0f / den;
        float hv[8];
        #pragma unroll
        for (int j = 0; j < 8; j++) hv[j] = (ca * res[j] + cb * y[j]) * inv;
        float h2 = inv * inv * (ca * ca * x2 + 2.0f * ca * cb * xy + cb * cb * y2);

        float n = fmaxf(sqrtf(h2), MIN_NORM);          // proj (analytic)
        if (n > MAXNORM) {
            float g = MAXNORM / n;
            #pragma unroll
            for (int j = 0; j < 8; j++) hv[j] *= g;
            h2 = MAXNORM * MAXNORM;
        }
        float pn = fmaxf(sqrtf(h2), MIN_NORM);         // logmap0 (analytic)
        float ls = artanh_clip(pn) / pn;

        __half2 o0 = __floats2half2_rn(hv[0] * ls, hv[1] * ls);
        __half2 o1 = __floats2half2_rn(hv[2] * ls, hv[3] * ls);
        __half2 o2 = __floats2half2_rn(hv[4] * ls, hv[5] * ls);
        __half2 o3 = __floats2half2_rn(hv[6] * ls, hv[7] * ls);
        uint2 ovA = make_uint2(*(uint32_t*)&o0, *(uint32_t*)&o1);
        uint2 ovB = make_uint2(*(uint32_t*)&o2, *(uint32_t*)&o3);
        *(uint2*)&g_xt[(size_t)row * DIM + c0]       = ovA;
        *(uint2*)&g_xt[(size_t)row * DIM + c0 + 128] = ovB;
    }
}

// ---------------- aggregation: warp-per-row, 4-edge MLP batches ----------
__global__ __launch_bounds__(256) void agg_k(float* __restrict__ out_opt, int n) {
    int w = threadIdx.x >> 5, lane = threadIdx.x & 31;
    int i = blockIdx.x * 8 + w;
    if (i >= n) return;
    int deg = min(g_cnt[i], BKT);
    const u64* bkt = &g_bkt[(size_t)i * BKT];

    float acc[8];
    #pragma unroll
    for (int j = 0; j < 8; j++) acc[j] = 0.0f;

    for (int base = 0; base < deg; base += 32) {
        int cnt = min(32, deg - base);
        int   myi = 0;
        float myw = 0.0f;
        if (lane < cnt) {
            u64 pair = bkt[base + lane];
            myi = (int)(uint32_t)pair;
            myw = __uint_as_float((uint32_t)(pair >> 32));
        }
        int e = 0;
        for (; e + 4 <= cnt; e += 4) {
            int   s0 = __shfl_sync(0xffffffffu, myi, e + 0);
            int   s1 = __shfl_sync(0xffffffffu, myi, e + 1);
            int   s2 = __shfl_sync(0xffffffffu, myi, e + 2);
            int   s3 = __shfl_sync(0xffffffffu, myi, e + 3);
            float w0 = __shfl_sync(0xffffffffu, myw, e + 0);
            float w1 = __shfl_sync(0xffffffffu, myw, e + 1);
            float w2 = __shfl_sync(0xffffffffu, myw, e + 2);
            float w3 = __shfl_sync(0xffffffffu, myw, e + 3);
            uint4 r0 = *(const uint4*)&g_xt[(size_t)s0 * DIM + lane * 8];
            uint4 r1 = *(const uint4*)&g_xt[(size_t)s1 * DIM + lane * 8];
            uint4 r2 = *(const uint4*)&g_xt[(size_t)s2 * DIM + lane * 8];
            uint4 r3 = *(const uint4*)&g_xt[(size_t)s3 * DIM + lane * 8];
            {
                float2 p0 = __half22float2(*(__half2*)&r0.x);
                float2 p1 = __half22float2(*(__half2*)&r0.y);
                float2 p2 = __half22float2(*(__half2*)&r0.z);
                float2 p3 = __half22float2(*(__half2*)&r0.w);
                acc[0] = fmaf(w0, p0.x, acc[0]); acc[1] = fmaf(w0, p0.y, acc[1]);
                acc[2] = fmaf(w0, p1.x, acc[2]); acc[3] = fmaf(w0, p1.y, acc[3]);
                acc[4] = fmaf(w0, p2.x, acc[4]); acc[5] = fmaf(w0, p2.y, acc[5]);
                acc[6] = fmaf(w0, p3.x, acc[6]); acc[7] = fmaf(w0, p3.y, acc[7]);
            }
            {
                float2 p0 = __half22float2(*(__half2*)&r1.x);
                float2 p1 = __half22float2(*(__half2*)&r1.y);
                float2 p2 = __half22float2(*(__half2*)&r1.z);
                float2 p3 = __half22float2(*(__half2*)&r1.w);
                acc[0] = fmaf(w1, p0.x, acc[0]); acc[1] = fmaf(w1, p0.y, acc[1]);
                acc[2] = fmaf(w1, p1.x, acc[2]); acc[3] = fmaf(w1, p1.y, acc[3]);
                acc[4] = fmaf(w1, p2.x, acc[4]); acc[5] = fmaf(w1, p2.y, acc[5]);
                acc[6] = fmaf(w1, p3.x, acc[6]); acc[7] = fmaf(w1, p3.y, acc[7]);
            }
            {
                float2 p0 = __half22float2(*(__half2*)&r2.x);
                float2 p1 = __half22float2(*(__half2*)&r2.y);
                float2 p2 = __half22float2(*(__half2*)&r2.z);
                float2 p3 = __half22float2(*(__half2*)&r2.w);
                acc[0] = fmaf(w2, p0.x, acc[0]); acc[1] = fmaf(w2, p0.y, acc[1]);
                acc[2] = fmaf(w2, p1.x, acc[2]); acc[3] = fmaf(w2, p1.y, acc[3]);
                acc[4] = fmaf(w2, p2.x, acc[4]); acc[5] = fmaf(w2, p2.y, acc[5]);
                acc[6] = fmaf(w2, p3.x, acc[6]); acc[7] = fmaf(w2, p3.y, acc[7]);
            }
            {
                float2 p0 = __half22float2(*(__half2*)&r3.x);
                float2 p1 = __half22float2(*(__half2*)&r3.y);
                float2 p2 = __half22float2(*(__half2*)&r3.z);
                float2 p3 = __half22float2(*(__half2*)&r3.w);
                acc[0] = fmaf(w3, p0.x, acc[0]); acc[1] = fmaf(w3, p0.y, acc[1]);
                acc[2] = fmaf(w3, p1.x, acc[2]); acc[3] = fmaf(w3, p1.y, acc[3]);
                acc[4] = fmaf(w3, p2.x, acc[4]); acc[5] = fmaf(w3, p2.y, acc[5]);
                acc[6] = fmaf(w3, p3.x, acc[6]); acc[7] = fmaf(w3, p3.y, acc[7]);
            }
        }
        for (; e < cnt; e++) {
            int   src = __shfl_sync(0xffffffffu, myi, e);
            float wt  = __shfl_sync(0xffffffffu, myw, e);
            uint4 raw = *(const uint4*)&g_xt[(size_t)src * DIM + lane * 8];
            float2 p0 = __half22float2(*(__half2*)&raw.x);
            float2 p1 = __half22float2(*(__half2*)&raw.y);
            float2 p2 = __half22float2(*(__half2*)&raw.z);
            float2 p3 = __half22float2(*(__half2*)&raw.w);
            acc[0] = fmaf(wt, p0.x, acc[0]); acc[1] = fmaf(wt, p0.y, acc[1]);
            acc[2] = fmaf(wt, p1.x, acc[2]); acc[3] = fmaf(wt, p1.y, acc[3]);
            acc[4] = fmaf(wt, p2.x, acc[4]); acc[5] = fmaf(wt, p2.y, acc[5]);
            acc[6] = fmaf(wt, p3.x, acc[6]); acc[7] = fmaf(wt, p3.y, acc[7]);
        }
    }

    // tail: 2 warp reductions, rest analytic
    float p = 0.0f;
    #pragma unroll
    for (int j = 0; j < 8; j++) p = fmaf(acc[j], acc[j], p);
    float s1 = wsum(p);                                // reduction #1
    float n1 = fmaxf(sqrtf(s1), MIN_NORM);
    float f1 = tanhf(n1) / n1;                         // expmap0
    float s  = s1 * f1 * f1;
    float n2 = fmaxf(sqrtf(s), MIN_NORM);              // proj (analytic)
    if (n2 > MAXNORM) { f1 *= MAXNORM / n2; s = MAXNORM * MAXNORM; }
    float n3 = fmaxf(sqrtf(s), MIN_NORM);              // logmap0 (analytic)
    float ls = artanh_clip(n3) / n3;
    float g1 = f1 * ls;
    #pragma unroll
    for (int j = 0; j < 8; j++) acc[j] = fmaxf(acc[j] * g1, 0.0f);  // relu

    p = 0.0f;
    #pragma unroll
    for (int j = 0; j < 8; j++) p = fmaf(acc[j], acc[j], p);
    float s5 = wsum(p);                                // reduction #2
    float n5 = fmaxf(sqrtf(s5), MIN_NORM);
    float f2 = tanhf(n5) / n5;                         // expmap0
    s = s5 * f2 * f2;
    float n6 = fmaxf(sqrtf(s), MIN_NORM);              // proj (analytic)
    if (n6 > MAXNORM) { f2 *= MAXNORM / n6; s = MAXNORM * MAXNORM; }
    #pragma unroll
    for (int j = 0; j < 8; j++) acc[j] *= f2;

    float4 o0 = make_float4(acc[0], acc[1], acc[2], acc[3]);
    float4 o1 = make_float4(acc[4], acc[5], acc[6], acc[7]);
    if (out_opt) {
        *(float4*)&out_opt[(size_t)i * DIM + lane * 8]     = o0;
        *(float4*)&out_opt[(size_t)i * DIM + lane * 8 + 4] = o1;
    } else {
        *(float4*)&g_h[(size_t)i * DIM + lane * 8]     = o0;
        *(float4*)&g_h[(size_t)i * DIM + lane * 8 + 4] = o1;
        if (lane == 0) g_x2[i] = s;
    }
}

// ---------------- launch ----------------
extern "C" void kernel_launch(void* const* d_in, const int* in_sizes, int n_in,
                              void* d_out, int out_size) {
    const float* x    = (const float*)d_in[0];
    const float* W1   = (const float*)d_in[1];
    const float* b1   = (const float*)d_in[2];
    const float* W2   = (const float*)d_in[3];
    const float* b2   = (const float*)d_in[4];
    const float* ew   = (const float*)d_in[5];
    const int*   esrc = (const int*)d_in[6];
    const int*   edst = (const int*)d_in[7];
    float*       out  = (float*)d_out;

    int n = in_sizes[0] / DIM;   // 10000
    int E = in_sizes[5];         // 320000

    // Fork the bucket build onto a side stream; overlap with init + gemm1.
    // Streams/events created only on non-replay calls; never destroyed here.
    cudaStream_t s2;
    cudaEvent_t e1, e2;
    cudaStreamCreateWithFlags(&s2, cudaStreamNonBlocking);
    cudaEventCreateWithFlags(&e1, cudaEventDisableTiming);
    cudaEventCreateWithFlags(&e2, cudaEventDisableTiming);

    // kernel-launch order: init(0), zero(1), fillb(2), gemm1(3), agg1(4),
    // gemm2(5) <- ncu -s 5 profiles the GEMM, agg2(6)
    init_k<<<(n + 2 + 7) / 8, 256>>>(x, b1, b2, n);

    cudaEventRecord(e1, 0);
    cudaStreamWaitEvent(s2, e1, 0);
    zero_k<<<(n + 255) / 256, 256, 0, s2>>>(n);
    fillb_k<<<(E + 255) / 256, 256, 0, s2>>>(esrc, edst, ew, E);
    cudaEventRecord(e2, s2);

    int gblocks = (n + GBM - 1) / GBM;   // 139

    gemm_fused_k<<<gblocks, 256>>>(W1, 0, n);

    cudaStreamWaitEvent(0, e2, 0);
    agg_k<<<(n + 7) / 8, 256>>>(nullptr, n);

    gemm_fused_k<<<gblocks, 256>>>(W2, 1, n);
    agg_k<<<(n + 7) / 8, 256>>>(out, n);
}

// round 16
// speedup vs baseline: 2.1756x; 1.0162x over previous
#include <cuda_runtime.h>
#include <cuda_fp16.h>
#include <cstdint>

#define N_NODES 10000
#define N_PAD   (N_NODES + 8)
#define DIM     256
#define E_MAX   320000
#define BKT     96            // bucket capacity per node (Poisson(32): mean+11σ)

#define MIN_NORM 1e-15f
#define MAXNORM  0.996f      // (1 - 4e-3)/sqrt(c), c = 1

// ---------------- device scratch (no allocations allowed) ----------------
typedef unsigned long long u64;

__device__ float   g_h  [N_PAD * DIM];      // current hyperbolic features (fp32, padded)
__device__ __half  g_xt [N_NODES * DIM];    // tangent features (fp16)
__device__ float   g_x2 [N_PAD];            // sumsq of each g_h row
__device__ int     g_cnt[N_NODES];          // per-node degree counter
__device__ u64     g_bkt[N_NODES * BKT];    // packed (src, weight) pairs
__device__ float   g_bias[2][DIM];
__device__ float   g_by2[2];                // sumsq of hyp_bias per layer

// ---------------- packed f32x2 helpers (sm_100+ PTX) ------
#define FMA2(d, a, b, c) \
    asm("fma.rn.f32x2 %0, %1, %2, %3;" : "=l"(d) : "l"(a), "l"(b), "l"(c))

__device__ __forceinline__ u64 pack_dup(float a) {
    u64 r;
    asm("mov.b64 %0, {%1, %1};" : "=l"(r) : "r"(__float_as_uint(a)));
    return r;
}
__device__ __forceinline__ float lo_f(u64 v) { return __uint_as_float((uint32_t)v); }
__device__ __forceinline__ float hi_f(u64 v) { return __uint_as_float((uint32_t)(v >> 32)); }

// ---------------- math helpers ----------------
__device__ __forceinline__ float artanh_clip(float x) {
    x = fminf(fmaxf(x, -1.0f + 1e-7f), 1.0f - 1e-7f);
    return atanhf(x);
}

__device__ __forceinline__ float wsum(float v) {
    #pragma unroll
    for (int o = 16; o > 0; o >>= 1) v += __shfl_xor_sync(0xffffffffu, v, o);
    return v;
}

// ---------------- bucket build ----------------
__global__ void zero_k(int n) {
    int i = blockIdx.x * blockDim.x + threadIdx.x;
    if (i < n) g_cnt[i] = 0;
}

__global__ void fillb_k(const int* __restrict__ src, const int* __restrict__ dst,
                        const float* __restrict__ w, int E) {
    int e = blockIdx.x * blockDim.x + threadIdx.x;
    if (e < E) {
        int d = dst[e];
        int slot = atomicAdd(&g_cnt[d], 1);
        if (slot < BKT) {
            u64 pair = (u64)(uint32_t)src[e] | ((u64)__float_as_uint(w[e]) << 32);
            g_bkt[(size_t)d * BKT + slot] = pair;
        }
    }
}

// ---------------- init: warp-per-row, barrier-free ----------
__global__ void init_k(const float* __restrict__ x,
                       const float* __restrict__ b1,
                       const float* __restrict__ b2, int n) {
    int w = threadIdx.x >> 5, lane = threadIdx.x & 31;
    int i = blockIdx.x * 8 + w;
    if (i >= n + 2) return;
    bool is_bias = (i >= n);
    const float* srcv = is_bias ? ((i == n) ? b1 : b2) : x + (size_t)i * DIM;

    float4 v0 = *(const float4*)&srcv[lane * 8];
    float4 v1 = *(const float4*)&srcv[lane * 8 + 4];

    float p = v0.x * v0.x + v0.y * v0.y + v0.z * v0.z + v0.w * v0.w
            + v1.x * v1.x + v1.y * v1.y + v1.z * v1.z + v1.w * v1.w;
    float s1 = wsum(p);
    float nn = fmaxf(sqrtf(s1), MIN_NORM);
    float f  = tanhf(nn) / nn;                 // expmap0
    float s  = s1 * f * f;
    float n2 = fmaxf(sqrtf(s), MIN_NORM);      // proj (analytic)
    if (n2 > MAXNORM) { f *= MAXNORM / n2; s = MAXNORM * MAXNORM; }
    v0.x *= f; v0.y *= f; v0.z *= f; v0.w *= f;
    v1.x *= f; v1.y *= f; v1.z *= f; v1.w *= f;

    if (is_bias) {
        int L = i - n;
        *(float4*)&g_bias[L][lane * 8]     = v0;
        *(float4*)&g_bias[L][lane * 8 + 4] = v1;
        if (lane == 0) g_by2[L] = s;
    } else {
        *(float4*)&g_h[(size_t)i * DIM + lane * 8]     = v0;
        *(float4*)&g_h[(size_t)i * DIM + lane * 8 + 4] = v1;
        if (lane == 0) g_x2[i] = s;
    }
}

// ---------------- fused GEMM (f32x2) + HypLinear tail -> g_xt ----------
// mx = h @ W^T. BM=72 rows/CTA, grid=139 (one balanced wave), 512 threads.
// Warp w: rowgrp rg=w>>1 (9 rows), colgrp cg=w&1 (128 cols). 4 warps/SMSP.
// A stored in smem PRE-DUPLICATED as f32x2 (loader packs once); mainloop is
// 6 LDS + 18 FMA2 per k per warp, zero movs -> fma-pipe-bound.
// B pairs read directly as ulonglong2 (contiguous floats = packed operand).
#define GBM 72
#define RPW 9
#define GBK 16
#define A2ST 12                // u64 stride per row-group (96 B, 16B-aligned)
#define A2P  (8 * A2ST)        // 96 u64 per k-slice
#define BP   260               // 1040 B row stride (16B aligned)

__global__ __launch_bounds__(512) void gemm_fused_k(const float* __restrict__ W,
                                                    int layer, int M) {
    __shared__ u64   As2[GBK][A2P];       // 12.3 KB, A values duplicated
    __shared__ float Bs[GBK][BP];         // 16.6 KB
    __shared__ float Ps[16][RPW + 3];     // half-row msq partials
    __shared__ float Qs[16][RPW + 3];     // half-row (mx . y) partials

    int tid = threadIdx.x;
    int bm  = blockIdx.x * GBM;
    int lane = tid & 31;
    int w    = tid >> 5;       // 0..15
    int rg   = w >> 1;         // row group 0..7
    int cg   = w & 1;          // col group 0..1
    int c0   = 4 * lane + 128 * cg;

    u64 acc[RPW][2];
    #pragma unroll
    for (int i = 0; i < RPW; i++) { acc[i][0] = 0ull; acc[i][1] = 0ull; }

    // loader indices
    int a_r = tid >> 2;            // 0..127 (use <72*4/4=288 threads)
    int a_k = (tid & 3) << 2;      // 0,4,8,12
    int b_j = tid >> 1;            // 0..255
    int b_k = (tid & 1) << 3;      // 0 or 8

    for (int k0 = 0; k0 < DIM; k0 += GBK) {
        // A tile: 72 rows x 16 k, duplicated into u64
        if (tid < 288) {
            int r = a_r;
            float4 v = *(const float4*)&g_h[(size_t)(bm + r) * DIM + k0 + a_k];
            int cm = (r / RPW) * A2ST + (r % RPW);
            As2[a_k + 0][cm] = pack_dup(v.x);
            As2[a_k + 1][cm] = pack_dup(v.y);
            As2[a_k + 2][cm] = pack_dup(v.z);
            As2[a_k + 3][cm] = pack_dup(v.w);
        }
        // B tile: 256 cols x 16 k (2 float4 per thread)
        {
            float4 v0 = *(const float4*)&W[(size_t)b_j * DIM + k0 + b_k];
            float4 v1 = *(const float4*)&W[(size_t)b_j * DIM + k0 + b_k + 4];
            Bs[b_k + 0][b_j] = v0.x;
            Bs[b_k + 1][b_j] = v0.y;
            Bs[b_k + 2][b_j] = v0.z;
            Bs[b_k + 3][b_j] = v0.w;
            Bs[b_k + 4][b_j] = v1.x;
            Bs[b_k + 5][b_j] = v1.y;
            Bs[b_k + 6][b_j] = v1.z;
            Bs[b_k + 7][b_j] = v1.w;
        }
        __syncthreads();
        #pragma unroll
        for (int k = 0; k < GBK; k++) {
            const u64* arow = &As2[k][rg * A2ST];
            ulonglong2 a01 = *(const ulonglong2*)(arow + 0);   // broadcast
            ulonglong2 a23 = *(const ulonglong2*)(arow + 2);
            ulonglong2 a45 = *(const ulonglong2*)(arow + 4);
            ulonglong2 a67 = *(const ulonglong2*)(arow + 6);
            u64        a8  = arow[8];
            ulonglong2 bp  = *(const ulonglong2*)&Bs[k][c0];   // 16B lane stride
            FMA2(acc[0][0], a01.x, bp.x, acc[0][0]);
            FMA2(acc[0][1], a01.x, bp.y, acc[0][1]);
            FMA2(acc[1][0], a01.y, bp.x, acc[1][0]);
            FMA2(acc[1][1], a01.y, bp.y, acc[1][1]);
            FMA2(acc[2][0], a23.x, bp.x, acc[2][0]);
            FMA2(acc[2][1], a23.x, bp.y, acc[2][1]);
            FMA2(acc[3][0], a23.y, bp.x, acc[3][0]);
            FMA2(acc[3][1], a23.y, bp.y, acc[3][1]);
            FMA2(acc[4][0], a45.x, bp.x, acc[4][0]);
            FMA2(acc[4][1], a45.x, bp.y, acc[4][1]);
            FMA2(acc[5][0], a45.y, bp.x, acc[5][0]);
            FMA2(acc[5][1], a45.y, bp.y, acc[5][1]);
            FMA2(acc[6][0], a67.x, bp.x, acc[6][0]);
            FMA2(acc[6][1], a67.x, bp.y, acc[6][1]);
            FMA2(acc[7][0], a67.y, bp.x, acc[7][0]);
            FMA2(acc[7][1], a67.y, bp.y, acc[7][1]);
            FMA2(acc[8][0], a8,    bp.x, acc[8][0]);
            FMA2(acc[8][1], a8,    bp.y, acc[8][1]);
        }
        __syncthreads();
    }

    // ---- epilogue: cross-warp partials + per-row scalar chain ----
    float4 yv = *(const float4*)&g_bias[layer][c0];
    float y2 = g_by2[layer];

    // phase 1: half-row partial sums (msq, mx.y)
    #pragma unroll
    for (int i = 0; i < RPW; i++) {
        float m0 = lo_f(acc[i][0]), m1 = hi_f(acc[i][0]);
        float m2 = lo_f(acc[i][1]), m3 = hi_f(acc[i][1]);
        float msq = fmaf(m0, m0, fmaf(m1, m1, fmaf(m2, m2, m3 * m3)));
        float mxy = fmaf(m0, yv.x, fmaf(m1, yv.y, fmaf(m2, yv.z, m3 * yv.w)));
        msq = wsum(msq);
        mxy = wsum(mxy);
        if (lane == 0) { Ps[w][i] = msq; Qs[w][i] = mxy; }
    }
    __syncthreads();

    // phase 2: full-row scalars (canonical order), out = alpha*mx + beta*y
    #pragma unroll
    for (int i = 0; i < RPW; i++) {
        int row = bm + rg * RPW + i;
        if (row >= M) continue;
        int we = w & ~1, wo = w | 1;
        float m2s = Ps[we][i] + Ps[wo][i];
        float mxy = Qs[we][i] + Qs[wo][i];

        float t, x2;
        if (m2s == 0.0f) {
            t = 0.0f; x2 = 0.0f;
        } else {
            float x_norm = fmaxf(sqrtf(g_x2[row]), MIN_NORM);
            float mxn = fmaxf(sqrtf(m2s), MIN_NORM);
            t = tanhf(mxn / x_norm * artanh_clip(x_norm)) / mxn;
            x2 = m2s * t * t;
            float nn = fmaxf(sqrtf(x2), MIN_NORM);       // proj (analytic)
            if (nn > MAXNORM) { t *= MAXNORM / nn; x2 = MAXNORM * MAXNORM; }
        }
        float xy = t * mxy;
        float ca  = 1.0f + 2.0f * xy + y2;
        float cb  = 1.0f - x2;
        float den = fmaxf(1.0f + 2.0f * xy + x2 * y2, MIN_NORM);
        float inv = 1.0f / den;
        float h2 = inv * inv * (ca * ca * x2 + 2.0f * ca * cb * xy + cb * cb * y2);
        float g = 1.0f;
        float nn = fmaxf(sqrtf(h2), MIN_NORM);           // proj (analytic)
        if (nn > MAXNORM) { g = MAXNORM / nn; h2 = MAXNORM * MAXNORM; }
        float pn = fmaxf(sqrtf(h2), MIN_NORM);           // logmap0 (analytic)
        float ls = artanh_clip(pn) / pn;
        float alpha = ca * inv * t * g * ls;
        float beta  = cb * inv * g * ls;

        float m0 = lo_f(acc[i][0]), m1 = hi_f(acc[i][0]);
        float m2 = lo_f(acc[i][1]), m3 = hi_f(acc[i][1]);
        __half2 o0 = __floats2half2_rn(fmaf(alpha, m0, beta * yv.x),
                                       fmaf(alpha, m1, beta * yv.y));
        __half2 o1 = __floats2half2_rn(fmaf(alpha, m2, beta * yv.z),
                                       fmaf(alpha, m3, beta * yv.w));
        uint2 ov = make_uint2(*(uint32_t*)&o0, *(uint32_t*)&o1);
        *(uint2*)&g_xt[(size_t)row * DIM + c0] = ov;
    }
}

// ---------------- aggregation: warp-per-row, 4-edge MLP batches ----------
__global__ __launch_bounds__(256) void agg_k(float* __restrict__ out_opt, int n) {
    int w = threadIdx.x >> 5, lane = threadIdx.x & 31;
    int i = blockIdx.x * 8 + w;
    if (i >= n) return;
    int deg = min(g_cnt[i], BKT);
    const u64* bkt = &g_bkt[(size_t)i * BKT];

    float acc[8];
    #pragma unroll
    for (int j = 0; j < 8; j++) acc[j] = 0.0f;

    for (int base = 0; base < deg; base += 32) {
        int cnt = min(32, deg - base);
        int   myi = 0;
        float myw = 0.0f;
        if (lane < cnt) {
            u64 pair = bkt[base + lane];
            myi = (int)(uint32_t)pair;
            myw = __uint_as_float((uint32_t)(pair >> 32));
        }
        int e = 0;
        for (; e + 4 <= cnt; e += 4) {
            int   s0 = __shfl_sync(0xffffffffu, myi, e + 0);
            int   s1 = __shfl_sync(0xffffffffu, myi, e + 1);
            int   s2 = __shfl_sync(0xffffffffu, myi, e + 2);
            int   s3 = __shfl_sync(0xffffffffu, myi, e + 3);
            float w0 = __shfl_sync(0xffffffffu, myw, e + 0);
            float w1 = __shfl_sync(0xffffffffu, myw, e + 1);
            float w2 = __shfl_sync(0xffffffffu, myw, e + 2);
            float w3 = __shfl_sync(0xffffffffu, myw, e + 3);
            uint4 r0 = *(const uint4*)&g_xt[(size_t)s0 * DIM + lane * 8];
            uint4 r1 = *(const uint4*)&g_xt[(size_t)s1 * DIM + lane * 8];
            uint4 r2 = *(const uint4*)&g_xt[(size_t)s2 * DIM + lane * 8];
            uint4 r3 = *(const uint4*)&g_xt[(size_t)s3 * DIM + lane * 8];
            {
                float2 p0 = __half22float2(*(__half2*)&r0.x);
                float2 p1 = __half22float2(*(__half2*)&r0.y);
                float2 p2 = __half22float2(*(__half2*)&r0.z);
                float2 p3 = __half22float2(*(__half2*)&r0.w);
                acc[0] = fmaf(w0, p0.x, acc[0]); acc[1] = fmaf(w0, p0.y, acc[1]);
                acc[2] = fmaf(w0, p1.x, acc[2]); acc[3] = fmaf(w0, p1.y, acc[3]);
                acc[4] = fmaf(w0, p2.x, acc[4]); acc[5] = fmaf(w0, p2.y, acc[5]);
                acc[6] = fmaf(w0, p3.x, acc[6]); acc[7] = fmaf(w0, p3.y, acc[7]);
            }
            {
                float2 p0 = __half22float2(*(__half2*)&r1.x);
                float2 p1 = __half22float2(*(__half2*)&r1.y);
                float2 p2 = __half22float2(*(__half2*)&r1.z);
                float2 p3 = __half22float2(*(__half2*)&r1.w);
                acc[0] = fmaf(w1, p0.x, acc[0]); acc[1] = fmaf(w1, p0.y, acc[1]);
                acc[2] = fmaf(w1, p1.x, acc[2]); acc[3] = fmaf(w1, p1.y, acc[3]);
                acc[4] = fmaf(w1, p2.x, acc[4]); acc[5] = fmaf(w1, p2.y, acc[5]);
                acc[6] = fmaf(w1, p3.x, acc[6]); acc[7] = fmaf(w1, p3.y, acc[7]);
            }
            {
                float2 p0 = __half22float2(*(__half2*)&r2.x);
                float2 p1 = __half22float2(*(__half2*)&r2.y);
                float2 p2 = __half22float2(*(__half2*)&r2.z);
                float2 p3 = __half22float2(*(__half2*)&r2.w);
                acc[0] = fmaf(w2, p0.x, acc[0]); acc[1] = fmaf(w2, p0.y, acc[1]);
                acc[2] = fmaf(w2, p1.x, acc[2]); acc[3] = fmaf(w2, p1.y, acc[3]);
                acc[4] = fmaf(w2, p2.x, acc[4]); acc[5] = fmaf(w2, p2.y, acc[5]);
                acc[6] = fmaf(w2, p3.x, acc[6]); acc[7] = fmaf(w2, p3.y, acc[7]);
            }
            {
                float2 p0 = __half22float2(*(__half2*)&r3.x);
                float2 p1 = __half22float2(*(__half2*)&r3.y);
                float2 p2 = __half22float2(*(__half2*)&r3.z);
                float2 p3 = __half22float2(*(__half2*)&r3.w);
                acc[0] = fmaf(w3, p0.x, acc[0]); acc[1] = fmaf(w3, p0.y, acc[1]);
                acc[2] = fmaf(w3, p1.x, acc[2]); acc[3] = fmaf(w3, p1.y, acc[3]);
                acc[4] = fmaf(w3, p2.x, acc[4]); acc[5] = fmaf(w3, p2.y, acc[5]);
                acc[6] = fmaf(w3, p3.x, acc[6]); acc[7] = fmaf(w3, p3.y, acc[7]);
            }
        }
        for (; e < cnt; e++) {
            int   src = __shfl_sync(0xffffffffu, myi, e);
            float wt  = __shfl_sync(0xffffffffu, myw, e);
            uint4 raw = *(const uint4*)&g_xt[(size_t)src * DIM + lane * 8];
            float2 p0 = __half22float2(*(__half2*)&raw.x);
            float2 p1 = __half22float2(*(__half2*)&raw.y);
            float2 p2 = __half22float2(*(__half2*)&raw.z);
            float2 p3 = __half22float2(*(__half2*)&raw.w);
            acc[0] = fmaf(wt, p0.x, acc[0]); acc[1] = fmaf(wt, p0.y, acc[1]);
            acc[2] = fmaf(wt, p1.x, acc[2]); acc[3] = fmaf(wt, p1.y, acc[3]);
            acc[4] = fmaf(wt, p2.x, acc[4]); acc[5] = fmaf(wt, p2.y, acc[5]);
            acc[6] = fmaf(wt, p3.x, acc[6]); acc[7] = fmaf(wt, p3.y, acc[7]);
        }
    }

    // tail: 2 warp reductions, rest analytic
    float p = 0.0f;
    #pragma unroll
    for (int j = 0; j < 8; j++) p = fmaf(acc[j], acc[j], p);
    float s1 = wsum(p);                                // reduction #1
    float n1 = fmaxf(sqrtf(s1), MIN_NORM);
    float f1 = tanhf(n1) / n1;                         // expmap0
    float s  = s1 * f1 * f1;
    float n2 = fmaxf(sqrtf(s), MIN_NORM);              // proj (analytic)
    if (n2 > MAXNORM) { f1 *= MAXNORM / n2; s = MAXNORM * MAXNORM; }
    float n3 = fmaxf(sqrtf(s), MIN_NORM);              // logmap0 (analytic)
    float ls = artanh_clip(n3) / n3;
    float g1 = f1 * ls;
    #pragma unroll
    for (int j = 0; j < 8; j++) acc[j] = fmaxf(acc[j] * g1, 0.0f);  // relu

    p = 0.0f;
    #pragma unroll
    for (int j = 0; j < 8; j++) p = fmaf(acc[j], acc[j], p);
    float s5 = wsum(p);                                // reduction #2
    float n5 = fmaxf(sqrtf(s5), MIN_NORM);
    float f2 = tanhf(n5) / n5;                         // expmap0
    s = s5 * f2 * f2;
    float n6 = fmaxf(sqrtf(s), MIN_NORM);              // proj (analytic)
    if (n6 > MAXNORM) { f2 *= MAXNORM / n6; s = MAXNORM * MAXNORM; }
    #pragma unroll
    for (int j = 0; j < 8; j++) acc[j] *= f2;

    float4 o0 = make_float4(acc[0], acc[1], acc[2], acc[3]);
    float4 o1 = make_float4(acc[4], acc[5], acc[6], acc[7]);
    if (out_opt) {
        *(float4*)&out_opt[(size_t)i * DIM + lane * 8]     = o0;
        *(float4*)&out_opt[(size_t)i * DIM + lane * 8 + 4] = o1;
    } else {
        *(float4*)&g_h[(size_t)i * DIM + lane * 8]     = o0;
        *(float4*)&g_h[(size_t)i * DIM + lane * 8 + 4] = o1;
        if (lane == 0) g_x2[i] = s;
    }
}

// ---------------- launch ----------------
extern "C" void kernel_launch(void* const* d_in, const int* in_sizes, int n_in,
                              void* d_out, int out_size) {
    const float* x    = (const float*)d_in[0];
    const float* W1   = (const float*)d_in[1];
    const float* b1   = (const float*)d_in[2];
    const float* W2   = (const float*)d_in[3];
    const float* b2   = (const float*)d_in[4];
    const float* ew   = (const float*)d_in[5];
    const int*   esrc = (const int*)d_in[6];
    const int*   edst = (const int*)d_in[7];
    float*       out  = (float*)d_out;

    int n = in_sizes[0] / DIM;   // 10000
    int E = in_sizes[5];         // 320000

    // Fork the bucket build onto a side stream; overlap with init + gemm1.
    // Streams/events created only on non-replay calls; never destroyed here.
    cudaStream_t s2;
    cudaEvent_t e1, e2;
    cudaStreamCreateWithFlags(&s2, cudaStreamNonBlocking);
    cudaEventCreateWithFlags(&e1, cudaEventDisableTiming);
    cudaEventCreateWithFlags(&e2, cudaEventDisableTiming);

    // kernel-launch order: init(0), zero(1), fillb(2), gemm1(3), agg1(4),
    // gemm2(5) <- ncu -s 5 profiles the GEMM, agg2(6)
    init_k<<<(n + 2 + 7) / 8, 256>>>(x, b1, b2, n);

    cudaEventRecord(e1, 0);
    cudaStreamWaitEvent(s2, e1, 0);
    zero_k<<<(n + 255) / 256, 256, 0, s2>>>(n);
    fillb_k<<<(E + 255) / 256, 256, 0, s2>>>(esrc, edst, ew, E);
    cudaEventRecord(e2, s2);

    int gblocks = (n + GBM - 1) / GBM;   // 139

    gemm_fused_k<<<gblocks, 512>>>(W1, 0, n);

    cudaStreamWaitEvent(0, e2, 0);
    agg_k<<<(n + 7) / 8, 256>>>(nullptr, n);

    gemm_fused_k<<<gblocks, 512>>>(W2, 1, n);
    agg_k<<<(n + 7) / 8, 256>>>(out, n);
}